// round 1
// baseline (speedup 1.0000x reference)
#include <cuda_runtime.h>
#include <math.h>

// Shapes (fixed by the problem): B=8, C=128, 2C=256, H=W=128, N=H*W=16384
#define B_ 8
#define C_ 128
#define C2_ 256
#define HW_ 128
#define N_ 16384
#define EPS_ 1e-5f

// ---------------- scratch (device globals; no allocation allowed) ----------
__device__ float g_wT[9 * C2_ * C_];              // weights [tap][ci][co]
__device__ float g_avg[B_ * C2_];                 // global avg pool
__device__ float g_se[B_ * C2_];                  // SE gate
__device__ float g_y[(size_t)B_ * C_ * N_];       // conv+BN+ReLU output (= q)
__device__ float g_simp[(size_t)B_ * 32 * C_ * C_]; // split-K partials of Q Q^T
__device__ float g_p[B_ * C_ * C_];               // softmax probs

// ---------------- 1. weight transpose: [co][ci][kh][kw] -> [tap][ci][co] ----
__global__ void transpose_w_kernel(const float* __restrict__ conv_w) {
    int i = blockIdx.x * blockDim.x + threadIdx.x;
    if (i >= 9 * C2_ * C_) return;
    int co  = i & (C_ - 1);
    int ci  = (i >> 7) & (C2_ - 1);
    int tap = i >> 15;
    g_wT[i] = conv_w[(co * C2_ + ci) * 9 + tap];
}

// ---------------- 2. global average pool over concat(x1,x2) ----------------
__global__ void avgpool_kernel(const float* __restrict__ x1,
                               const float* __restrict__ x2) {
    int bc = blockIdx.x;             // b*256 + c
    int b = bc >> 8, c = bc & 255;
    const float* src = (c < C_) ? (x1 + ((size_t)(b * C_ + c)) * N_)
                                : (x2 + ((size_t)(b * C_ + (c - C_))) * N_);
    float s = 0.f;
    const float4* s4 = (const float4*)src;
    for (int i = threadIdx.x; i < N_ / 4; i += 256) {
        float4 v = s4[i];
        s += v.x + v.y + v.z + v.w;
    }
    // block reduce
    for (int o = 16; o; o >>= 1) s += __shfl_down_sync(0xffffffffu, s, o);
    __shared__ float ws[8];
    int lane = threadIdx.x & 31, wid = threadIdx.x >> 5;
    if (lane == 0) ws[wid] = s;
    __syncthreads();
    if (threadIdx.x == 0) {
        float t = 0.f;
        #pragma unroll
        for (int i = 0; i < 8; i++) t += ws[i];
        g_avg[bc] = t * (1.f / (float)N_);
    }
}

// ---------------- 3. SE MLP: relu(avg @ W1^T), sigmoid(h @ W2^T) -----------
__global__ void se_mlp_kernel(const float* __restrict__ se_w1,
                              const float* __restrict__ se_w2) {
    __shared__ float avg_s[C2_];
    __shared__ float h_s[32];
    int tid = threadIdx.x;
    for (int b = 0; b < B_; b++) {
        avg_s[tid] = g_avg[b * C2_ + tid];
        __syncthreads();
        if (tid < 32) {
            float s = 0.f;
            #pragma unroll 8
            for (int k = 0; k < C2_; k++) s += avg_s[k] * se_w1[tid * C2_ + k];
            h_s[tid] = fmaxf(s, 0.f);
        }
        __syncthreads();
        {
            float s = 0.f;
            #pragma unroll
            for (int j = 0; j < 32; j++) s += h_s[j] * se_w2[tid * 32 + j];
            g_se[b * C2_ + tid] = 1.f / (1.f + expf(-s));
        }
        __syncthreads();
    }
}

// ---------------- 4. conv 3x3 (SE fused on load) + BN + ReLU ---------------
// Implicit GEMM per (batch, output row): M=128 co x N=128 w, K=9*256.
__global__ __launch_bounds__(256, 2)
void conv_kernel(const float* __restrict__ x1, const float* __restrict__ x2,
                 const float* __restrict__ bn_gamma, const float* __restrict__ bn_beta,
                 const float* __restrict__ bn_mean, const float* __restrict__ bn_var) {
    const int h = blockIdx.x;
    const int b = blockIdx.y;
    __shared__ float As[8][C_];       // [kk][co]
    __shared__ float Bs[8][C_ + 4];   // [kk][n]
    const int tid = threadIdx.x;
    const int tm = tid >> 4;          // 0..15 (co group)
    const int tn = tid & 15;          // 0..15 (n group)
    float acc[8][8];
    #pragma unroll
    for (int i = 0; i < 8; i++)
        #pragma unroll
        for (int j = 0; j < 8; j++) acc[i][j] = 0.f;

    const float* xb1 = x1 + (size_t)b * C_ * N_;
    const float* xb2 = x2 + (size_t)b * C_ * N_;

    const int lkk = tid >> 5;         // 0..7  (loader k index)
    const int ln0 = (tid & 31) * 4;   // 0..124 (loader col base)

    for (int tap = 0; tap < 9; tap++) {
        const int kh = tap / 3 - 1;
        const int kw = tap % 3 - 1;
        const int hh = h + kh;
        if (hh < 0 || hh >= HW_) continue;   // block-uniform

        for (int cib = 0; cib < C2_; cib += 8) {
            // A tile: weights (coalesced from transposed layout)
            {
                const float4 w4 = *(const float4*)(g_wT + (size_t)(tap * C2_ + cib + lkk) * C_ + ln0);
                *(float4*)&As[lkk][ln0] = w4;
            }
            // B tile: SE-scaled, shifted input row
            {
                const int ci = cib + lkk;
                const float s = g_se[b * C2_ + ci];
                const float* src = ((ci < C_) ? (xb1 + (size_t)ci * N_)
                                              : (xb2 + (size_t)(ci - C_) * N_)) + hh * HW_;
                #pragma unroll
                for (int e = 0; e < 4; e++) {
                    const int n = ln0 + e;
                    const int wsrc = n + kw;
                    float v = 0.f;
                    if (wsrc >= 0 && wsrc < HW_) v = src[wsrc] * s;
                    Bs[lkk][n] = v;
                }
            }
            __syncthreads();
            #pragma unroll
            for (int kk = 0; kk < 8; kk++) {
                float a[8], bb[8];
                float4 a0 = *(const float4*)&As[kk][tm * 8];
                float4 a1 = *(const float4*)&As[kk][tm * 8 + 4];
                float4 b0 = *(const float4*)&Bs[kk][tn * 8];
                float4 b1 = *(const float4*)&Bs[kk][tn * 8 + 4];
                a[0]=a0.x; a[1]=a0.y; a[2]=a0.z; a[3]=a0.w;
                a[4]=a1.x; a[5]=a1.y; a[6]=a1.z; a[7]=a1.w;
                bb[0]=b0.x; bb[1]=b0.y; bb[2]=b0.z; bb[3]=b0.w;
                bb[4]=b1.x; bb[5]=b1.y; bb[6]=b1.z; bb[7]=b1.w;
                #pragma unroll
                for (int i = 0; i < 8; i++)
                    #pragma unroll
                    for (int j = 0; j < 8; j++)
                        acc[i][j] = fmaf(a[i], bb[j], acc[i][j]);
            }
            __syncthreads();
        }
    }

    // epilogue: BN (eval) + ReLU
    #pragma unroll
    for (int i = 0; i < 8; i++) {
        const int co = tm * 8 + i;
        const float inv = bn_gamma[co] * rsqrtf(bn_var[co] + EPS_);
        const float bias = bn_beta[co] - bn_mean[co] * inv;
        float* dst = g_y + (((size_t)b * C_ + co) * N_) + (size_t)h * HW_ + tn * 8;
        #pragma unroll
        for (int j = 0; j < 8; j++)
            dst[j] = fmaxf(acc[i][j] * inv + bias, 0.f);
    }
}

// ---------------- 5. sim = Q Q^T, split-K (deterministic partials) ---------
__global__ __launch_bounds__(256, 2)
void sim_kernel() {
    const int split = blockIdx.x;   // 0..31, each K chunk = 512
    const int b = blockIdx.y;
    const float* q = g_y + (size_t)b * C_ * N_;
    const int k0 = split * 512;

    __shared__ float Qs[8][C_ + 4];  // [kk][row]
    const int tid = threadIdx.x;
    const int tm = tid >> 4, tn = tid & 15;
    float acc[8][8];
    #pragma unroll
    for (int i = 0; i < 8; i++)
        #pragma unroll
        for (int j = 0; j < 8; j++) acc[i][j] = 0.f;

    const int lr = tid >> 1;          // row 0..127
    const int lk4 = (tid & 1) * 4;    // kk base 0 or 4

    for (int kb = 0; kb < 512; kb += 8) {
        {
            float4 v = *(const float4*)(q + (size_t)lr * N_ + k0 + kb + lk4);
            Qs[lk4 + 0][lr] = v.x; Qs[lk4 + 1][lr] = v.y;
            Qs[lk4 + 2][lr] = v.z; Qs[lk4 + 3][lr] = v.w;
        }
        __syncthreads();
        #pragma unroll
        for (int kk = 0; kk < 8; kk++) {
            float a[8], bb[8];
            float4 a0 = *(const float4*)&Qs[kk][tm * 8];
            float4 a1 = *(const float4*)&Qs[kk][tm * 8 + 4];
            float4 b0 = *(const float4*)&Qs[kk][tn * 8];
            float4 b1 = *(const float4*)&Qs[kk][tn * 8 + 4];
            a[0]=a0.x; a[1]=a0.y; a[2]=a0.z; a[3]=a0.w;
            a[4]=a1.x; a[5]=a1.y; a[6]=a1.z; a[7]=a1.w;
            bb[0]=b0.x; bb[1]=b0.y; bb[2]=b0.z; bb[3]=b0.w;
            bb[4]=b1.x; bb[5]=b1.y; bb[6]=b1.z; bb[7]=b1.w;
            #pragma unroll
            for (int i = 0; i < 8; i++)
                #pragma unroll
                for (int j = 0; j < 8; j++)
                    acc[i][j] = fmaf(a[i], bb[j], acc[i][j]);
        }
        __syncthreads();
    }

    float* dst = g_simp + (((size_t)(b * 32 + split)) * C_ * C_);
    #pragma unroll
    for (int i = 0; i < 8; i++)
        #pragma unroll
        for (int j = 0; j < 8; j++)
            dst[(tm * 8 + i) * C_ + tn * 8 + j] = acc[i][j];
}

// ---------------- 6. softmax(max - sim) == exp(min - sim)/sum --------------
__global__ void softmax_kernel() {
    const int c = blockIdx.x, b = blockIdx.y;
    const int d = threadIdx.x;   // 128 threads
    float s = 0.f;
    #pragma unroll 8
    for (int sp = 0; sp < 32; sp++)
        s += g_simp[(((size_t)(b * 32 + sp)) * C_ + c) * C_ + d];

    __shared__ float red[128];
    red[d] = s;
    __syncthreads();
    for (int st = 64; st > 0; st >>= 1) {
        if (d < st) red[d] = fminf(red[d], red[d + st]);
        __syncthreads();
    }
    const float mn = red[0];
    __syncthreads();
    const float e = expf(mn - s);
    red[d] = e;
    __syncthreads();
    for (int st = 64; st > 0; st >>= 1) {
        if (d < st) red[d] += red[d + st];
        __syncthreads();
    }
    g_p[(b * C_ + c) * C_ + d] = e / red[0];
}

// ---------------- 7. feat = P @ Q ; out = gamma*feat + y -------------------
__global__ __launch_bounds__(256, 2)
void feat_kernel(const float* __restrict__ gamma, float* __restrict__ out) {
    const int n0 = blockIdx.x * 128;   // pixel tile
    const int b = blockIdx.y;
    const float* q = g_y + (size_t)b * C_ * N_;
    const float* p = g_p + (size_t)b * C_ * C_;

    __shared__ float Ps[8][C_ + 4];   // [kk][c] = p[c][d0+kk]
    __shared__ float Qs[8][C_ + 4];   // [kk][n]
    const int tid = threadIdx.x;
    const int tm = tid >> 4, tn = tid & 15;
    float acc[8][8];
    #pragma unroll
    for (int i = 0; i < 8; i++)
        #pragma unroll
        for (int j = 0; j < 8; j++) acc[i][j] = 0.f;

    const int lc = tid >> 1, lk4 = (tid & 1) * 4;  // Ps loader
    const int lkk = tid >> 5, ln0 = (tid & 31) * 4; // Qs loader

    for (int d0 = 0; d0 < C_; d0 += 8) {
        {
            float4 v = *(const float4*)(p + lc * C_ + d0 + lk4);
            Ps[lk4 + 0][lc] = v.x; Ps[lk4 + 1][lc] = v.y;
            Ps[lk4 + 2][lc] = v.z; Ps[lk4 + 3][lc] = v.w;
        }
        {
            float4 v = *(const float4*)(q + (size_t)(d0 + lkk) * N_ + n0 + ln0);
            *(float4*)&Qs[lkk][ln0] = v;
        }
        __syncthreads();
        #pragma unroll
        for (int kk = 0; kk < 8; kk++) {
            float a[8], bb[8];
            float4 a0 = *(const float4*)&Ps[kk][tm * 8];
            float4 a1 = *(const float4*)&Ps[kk][tm * 8 + 4];
            float4 b0 = *(const float4*)&Qs[kk][tn * 8];
            float4 b1 = *(const float4*)&Qs[kk][tn * 8 + 4];
            a[0]=a0.x; a[1]=a0.y; a[2]=a0.z; a[3]=a0.w;
            a[4]=a1.x; a[5]=a1.y; a[6]=a1.z; a[7]=a1.w;
            bb[0]=b0.x; bb[1]=b0.y; bb[2]=b0.z; bb[3]=b0.w;
            bb[4]=b1.x; bb[5]=b1.y; bb[6]=b1.z; bb[7]=b1.w;
            #pragma unroll
            for (int i = 0; i < 8; i++)
                #pragma unroll
                for (int j = 0; j < 8; j++)
                    acc[i][j] = fmaf(a[i], bb[j], acc[i][j]);
        }
        __syncthreads();
    }

    const float g0 = gamma[0];
    #pragma unroll
    for (int i = 0; i < 8; i++) {
        const int c = tm * 8 + i;
        const size_t base = ((size_t)b * C_ + c) * N_ + n0 + tn * 8;
        #pragma unroll
        for (int j = 0; j < 8; j++)
            out[base + j] = g0 * acc[i][j] + g_y[base + j];
    }
}

// ---------------- launch ---------------------------------------------------
extern "C" void kernel_launch(void* const* d_in, const int* in_sizes, int n_in,
                              void* d_out, int out_size) {
    const float* x1       = (const float*)d_in[0];
    const float* x2       = (const float*)d_in[1];
    const float* se_w1    = (const float*)d_in[2];
    const float* se_w2    = (const float*)d_in[3];
    const float* conv_w   = (const float*)d_in[4];
    const float* bn_gamma = (const float*)d_in[5];
    const float* bn_beta  = (const float*)d_in[6];
    const float* bn_mean  = (const float*)d_in[7];
    const float* bn_var   = (const float*)d_in[8];
    const float* gamma    = (const float*)d_in[9];
    float* out = (float*)d_out;

    transpose_w_kernel<<<(9 * C2_ * C_ + 255) / 256, 256>>>(conv_w);
    avgpool_kernel<<<B_ * C2_, 256>>>(x1, x2);
    se_mlp_kernel<<<1, C2_>>>(se_w1, se_w2);
    conv_kernel<<<dim3(HW_, B_), 256>>>(x1, x2, bn_gamma, bn_beta, bn_mean, bn_var);
    sim_kernel<<<dim3(32, B_), 256>>>();
    softmax_kernel<<<dim3(C_, B_), 128>>>();
    feat_kernel<<<dim3(N_ / 128, B_), 256>>>(gamma, out);
}

// round 3
// speedup vs baseline: 1.6647x; 1.6647x over previous
#include <cuda_runtime.h>
#include <cstdint>
#include <math.h>

// Shapes: B=8, C=128, 2C=256, H=W=128, N=H*W=16384
#define B_ 8
#define C_ 128
#define C2_ 256
#define HW_ 128
#define N_ 16384
#define EPS_ 1e-5f

// ===================== tf32 helpers ========================================
__device__ __forceinline__ void split_tf32(float v, float& hf, float& lf) {
    uint32_t hb, lb;
    asm("cvt.rna.tf32.f32 %0, %1;" : "=r"(hb) : "f"(v));
    hf = __uint_as_float(hb);
    float lo = v - hf;
    asm("cvt.rna.tf32.f32 %0, %1;" : "=r"(lb) : "f"(lo));
    lf = __uint_as_float(lb);
}

__device__ __forceinline__ void mma1688(float4& d, const float4& a, float b0, float b1) {
    asm volatile(
        "mma.sync.aligned.m16n8k8.row.col.f32.tf32.tf32.f32 "
        "{%0,%1,%2,%3}, {%4,%5,%6,%7}, {%8,%9}, {%0,%1,%2,%3};"
        : "+f"(d.x), "+f"(d.y), "+f"(d.z), "+f"(d.w)
        : "r"(__float_as_uint(a.x)), "r"(__float_as_uint(a.y)),
          "r"(__float_as_uint(a.z)), "r"(__float_as_uint(a.w)),
          "r"(__float_as_uint(b0)), "r"(__float_as_uint(b1)));
}

// ===================== device scratch ======================================
// A fragments: [ks=tap*32+kc8][mt 0..7][split 0..1][lane 0..31] -> float4
// idx = ((ks*8 + mt)*2 + s)*32 + lane
__device__ __align__(16) float4 g_wfrag[288 * 8 * 2 * 32];
__device__ float g_avg[B_ * C2_];
__device__ float g_se[B_ * C2_];
__device__ __align__(16) float g_y[(size_t)B_ * C_ * N_];
__device__ __align__(16) float g_simp[(size_t)B_ * 32 * C_ * C_];
__device__ __align__(16) float g_p[B_ * C_ * C_];

// ===== 1. weight prep: conv_w [co][ci][tap] -> mma fragment order ==========
__global__ void prep_wfrag_kernel(const float* __restrict__ conv_w) {
    int idx = blockIdx.x * blockDim.x + threadIdx.x;
    if (idx >= 288 * 8 * 2 * 32) return;
    int lane = idx & 31;
    int s    = (idx >> 5) & 1;
    int mt   = (idx >> 6) & 7;
    int ks   = idx >> 9;          // 0..287
    int tap  = ks >> 5;
    int kc8  = ks & 31;
    int co = mt * 16 + (lane >> 2);
    int ci = kc8 * 8 + (lane & 3);
    float w00 = conv_w[((co    ) * C2_ + ci    ) * 9 + tap];
    float w10 = conv_w[((co + 8) * C2_ + ci    ) * 9 + tap];
    float w01 = conv_w[((co    ) * C2_ + ci + 4) * 9 + tap];
    float w11 = conv_w[((co + 8) * C2_ + ci + 4) * 9 + tap];
    float h00, l00, h10, l10, h01, l01, h11, l11;
    split_tf32(w00, h00, l00); split_tf32(w10, h10, l10);
    split_tf32(w01, h01, l01); split_tf32(w11, h11, l11);
    float4 v;
    if (s == 0) { v.x = h00; v.y = h10; v.z = h01; v.w = h11; }
    else        { v.x = l00; v.y = l10; v.z = l01; v.w = l11; }
    g_wfrag[idx] = v;
}

// ===== 2. global average pool over concat(x1,x2) ===========================
__global__ void avgpool_kernel(const float* __restrict__ x1,
                               const float* __restrict__ x2) {
    int bc = blockIdx.x;
    int b = bc >> 8, c = bc & 255;
    const float* src = (c < C_) ? (x1 + ((size_t)(b * C_ + c)) * N_)
                                : (x2 + ((size_t)(b * C_ + (c - C_))) * N_);
    float s = 0.f;
    const float4* s4 = (const float4*)src;
    for (int i = threadIdx.x; i < N_ / 4; i += 256) {
        float4 v = s4[i];
        s += v.x + v.y + v.z + v.w;
    }
    for (int o = 16; o; o >>= 1) s += __shfl_down_sync(0xffffffffu, s, o);
    __shared__ float ws[8];
    int lane = threadIdx.x & 31, wid = threadIdx.x >> 5;
    if (lane == 0) ws[wid] = s;
    __syncthreads();
    if (threadIdx.x == 0) {
        float t = 0.f;
        #pragma unroll
        for (int i = 0; i < 8; i++) t += ws[i];
        g_avg[bc] = t * (1.f / (float)N_);
    }
}

// ===== 3. SE MLP ============================================================
__global__ void se_mlp_kernel(const float* __restrict__ se_w1,
                              const float* __restrict__ se_w2) {
    __shared__ float avg_s[C2_];
    __shared__ float h_s[32];
    int tid = threadIdx.x;
    for (int b = 0; b < B_; b++) {
        avg_s[tid] = g_avg[b * C2_ + tid];
        __syncthreads();
        if (tid < 32) {
            float s = 0.f;
            #pragma unroll 8
            for (int k = 0; k < C2_; k++) s += avg_s[k] * se_w1[tid * C2_ + k];
            h_s[tid] = fmaxf(s, 0.f);
        }
        __syncthreads();
        {
            float s = 0.f;
            #pragma unroll
            for (int j = 0; j < 32; j++) s += h_s[j] * se_w2[tid * 32 + j];
            g_se[b * C2_ + tid] = 1.f / (1.f + expf(-s));
        }
        __syncthreads();
    }
}

// ===== 4. conv 3x3 via mma.sync tf32 (3-way split) + BN + ReLU =============
// Per CTA (b,h): D[co=128][w=128] = sum_k W[co][k]*X[w][k], k=(tap,ci), K=2304
// 8 warps: warpM = wid>>2 (2, 64 rows each), warpN = wid&3 (4, 32 cols each)
#define BS_STRIDE 136

__global__ void __launch_bounds__(256, 2)
conv_mma_kernel(const float* __restrict__ x1, const float* __restrict__ x2,
                const float* __restrict__ bn_gamma, const float* __restrict__ bn_beta,
                const float* __restrict__ bn_mean, const float* __restrict__ bn_var) {
    __shared__ float Bs_hi[32 * BS_STRIDE];
    __shared__ float Bs_lo[32 * BS_STRIDE];

    const int tid = threadIdx.x;
    const int wid = tid >> 5, lane = tid & 31;
    const int warpM = wid >> 2, warpN = wid & 3;
    const int h = blockIdx.x, b = blockIdx.y;

    float4 acc[4][4];
    #pragma unroll
    for (int m = 0; m < 4; m++)
        #pragma unroll
        for (int n = 0; n < 4; n++) acc[m][n] = make_float4(0.f, 0.f, 0.f, 0.f);

    // B-builder mapping: row r (ci-local), w = wbase + e*8 (bank-conflict-free)
    const int r = tid >> 3;
    const int wbase = tid & 7;

    // fragment LDS mapping
    const int tg = lane & 3;          // thread-in-group
    const int gp = lane >> 2;         // group id
    const int cbase = warpN * 32 + gp;

    for (int tap = 0; tap < 9; tap++) {
        const int hh = h + tap / 3 - 1;
        if (hh < 0 || hh >= HW_) continue;
        const int kw = tap % 3 - 1;

        for (int cib = 0; cib < 8; cib++) {
            __syncthreads();   // previous chunk fully consumed
            // ---- build B tile: X[w][k] (SE-scaled, hi/lo split) ----
            {
                const int ci = cib * 32 + r;
                const float se = g_se[b * C2_ + ci];
                const float* src = ((ci < C_) ? (x1 + ((size_t)(b * C_ + ci)) * N_)
                                              : (x2 + ((size_t)(b * C_ + ci - C_)) * N_))
                                   + (size_t)hh * HW_;
                #pragma unroll
                for (int e = 0; e < 16; e++) {
                    const int w = wbase + e * 8;
                    const int ws = w + kw;
                    float v = (ws >= 0 && ws < HW_) ? src[ws] * se : 0.f;
                    float hf, lf;
                    split_tf32(v, hf, lf);
                    Bs_hi[r * BS_STRIDE + w] = hf;
                    Bs_lo[r * BS_STRIDE + w] = lf;
                }
            }
            __syncthreads();

            // ---- 4 k8 steps ----
            #pragma unroll
            for (int j = 0; j < 4; j++) {
                const int ks = tap * 32 + cib * 4 + j;
                const int k0 = j * 8 + tg;

                // B fragments
                float bh[4][2], bl[4][2];
                #pragma unroll
                for (int nt = 0; nt < 4; nt++) {
                    bh[nt][0] = Bs_hi[(k0    ) * BS_STRIDE + cbase + nt * 8];
                    bh[nt][1] = Bs_hi[(k0 + 4) * BS_STRIDE + cbase + nt * 8];
                    bl[nt][0] = Bs_lo[(k0    ) * BS_STRIDE + cbase + nt * 8];
                    bl[nt][1] = Bs_lo[(k0 + 4) * BS_STRIDE + cbase + nt * 8];
                }

                // A hi fragments
                const size_t ofs = ((size_t)ks * 16 + warpM * 8) * 32 + lane;
                float4 ah[4];
                #pragma unroll
                for (int m = 0; m < 4; m++) ah[m] = g_wfrag[ofs + (size_t)(m * 2) * 32];

                #pragma unroll
                for (int m = 0; m < 4; m++)
                    #pragma unroll
                    for (int nt = 0; nt < 4; nt++)
                        mma1688(acc[m][nt], ah[m], bh[nt][0], bh[nt][1]);

                // A lo fragments (load early; consumed after ah*bl block)
                float4 al[4];
                #pragma unroll
                for (int m = 0; m < 4; m++) al[m] = g_wfrag[ofs + (size_t)(m * 2 + 1) * 32];

                #pragma unroll
                for (int m = 0; m < 4; m++)
                    #pragma unroll
                    for (int nt = 0; nt < 4; nt++)
                        mma1688(acc[m][nt], ah[m], bl[nt][0], bl[nt][1]);

                #pragma unroll
                for (int m = 0; m < 4; m++)
                    #pragma unroll
                    for (int nt = 0; nt < 4; nt++)
                        mma1688(acc[m][nt], al[m], bh[nt][0], bh[nt][1]);
            }
        }
    }

    // ---- epilogue: BN + ReLU, direct float2 stores ----
    #pragma unroll
    for (int m = 0; m < 4; m++) {
        const int co0 = warpM * 64 + m * 16 + gp;
        const int co1 = co0 + 8;
        const float inv0 = bn_gamma[co0] * rsqrtf(bn_var[co0] + EPS_);
        const float bia0 = bn_beta[co0] - bn_mean[co0] * inv0;
        const float inv1 = bn_gamma[co1] * rsqrtf(bn_var[co1] + EPS_);
        const float bia1 = bn_beta[co1] - bn_mean[co1] * inv1;
        #pragma unroll
        for (int nt = 0; nt < 4; nt++) {
            const int w = warpN * 32 + nt * 8 + tg * 2;
            float2 v0, v1;
            v0.x = fmaxf(acc[m][nt].x * inv0 + bia0, 0.f);
            v0.y = fmaxf(acc[m][nt].y * inv0 + bia0, 0.f);
            v1.x = fmaxf(acc[m][nt].z * inv1 + bia1, 0.f);
            v1.y = fmaxf(acc[m][nt].w * inv1 + bia1, 0.f);
            *(float2*)(g_y + ((size_t)(b * C_ + co0)) * N_ + (size_t)h * HW_ + w) = v0;
            *(float2*)(g_y + ((size_t)(b * C_ + co1)) * N_ + (size_t)h * HW_ + w) = v1;
        }
    }
}

// ===== 5. sim = Q Q^T, split-K (fp32 FFMA, deterministic partials) =========
__global__ __launch_bounds__(256, 2)
void sim_kernel() {
    const int split = blockIdx.x;
    const int b = blockIdx.y;
    const float* q = g_y + (size_t)b * C_ * N_;
    const int k0 = split * 512;

    __shared__ float Qs[8][C_ + 4];
    const int tid = threadIdx.x;
    const int tm = tid >> 4, tn = tid & 15;
    float acc[8][8];
    #pragma unroll
    for (int i = 0; i < 8; i++)
        #pragma unroll
        for (int j = 0; j < 8; j++) acc[i][j] = 0.f;

    const int lr = tid >> 1;
    const int lk4 = (tid & 1) * 4;

    for (int kb = 0; kb < 512; kb += 8) {
        {
            float4 v = *(const float4*)(q + (size_t)lr * N_ + k0 + kb + lk4);
            Qs[lk4 + 0][lr] = v.x; Qs[lk4 + 1][lr] = v.y;
            Qs[lk4 + 2][lr] = v.z; Qs[lk4 + 3][lr] = v.w;
        }
        __syncthreads();
        #pragma unroll
        for (int kk = 0; kk < 8; kk++) {
            float a[8], bb[8];
            float4 a0 = *(const float4*)&Qs[kk][tm * 8];
            float4 a1 = *(const float4*)&Qs[kk][tm * 8 + 4];
            float4 b0 = *(const float4*)&Qs[kk][tn * 8];
            float4 b1 = *(const float4*)&Qs[kk][tn * 8 + 4];
            a[0]=a0.x; a[1]=a0.y; a[2]=a0.z; a[3]=a0.w;
            a[4]=a1.x; a[5]=a1.y; a[6]=a1.z; a[7]=a1.w;
            bb[0]=b0.x; bb[1]=b0.y; bb[2]=b0.z; bb[3]=b0.w;
            bb[4]=b1.x; bb[5]=b1.y; bb[6]=b1.z; bb[7]=b1.w;
            #pragma unroll
            for (int i = 0; i < 8; i++)
                #pragma unroll
                for (int j = 0; j < 8; j++)
                    acc[i][j] = fmaf(a[i], bb[j], acc[i][j]);
        }
        __syncthreads();
    }

    float* dst = g_simp + (((size_t)(b * 32 + split)) * C_ * C_);
    #pragma unroll
    for (int i = 0; i < 8; i++)
        #pragma unroll
        for (int j = 0; j < 8; j++)
            dst[(tm * 8 + i) * C_ + tn * 8 + j] = acc[i][j];
}

// ===== 6. softmax(max - sim) == exp(min - sim)/sum =========================
__global__ void softmax_kernel() {
    const int c = blockIdx.x, b = blockIdx.y;
    const int d = threadIdx.x;
    float s = 0.f;
    #pragma unroll 8
    for (int sp = 0; sp < 32; sp++)
        s += g_simp[(((size_t)(b * 32 + sp)) * C_ + c) * C_ + d];

    __shared__ float red[128];
    red[d] = s;
    __syncthreads();
    for (int st = 64; st > 0; st >>= 1) {
        if (d < st) red[d] = fminf(red[d], red[d + st]);
        __syncthreads();
    }
    const float mn = red[0];
    __syncthreads();
    const float e = expf(mn - s);
    red[d] = e;
    __syncthreads();
    for (int st = 64; st > 0; st >>= 1) {
        if (d < st) red[d] += red[d + st];
        __syncthreads();
    }
    g_p[(b * C_ + c) * C_ + d] = e / red[0];
}

// ===== 7. feat = P @ Q ; out = gamma*feat + y ==============================
__global__ __launch_bounds__(256, 2)
void feat_kernel(const float* __restrict__ gamma, float* __restrict__ out) {
    const int n0 = blockIdx.x * 128;
    const int b = blockIdx.y;
    const float* q = g_y + (size_t)b * C_ * N_;
    const float* p = g_p + (size_t)b * C_ * C_;

    __shared__ float Ps[8][C_ + 4];
    __shared__ float Qs[8][C_ + 4];
    const int tid = threadIdx.x;
    const int tm = tid >> 4, tn = tid & 15;
    float acc[8][8];
    #pragma unroll
    for (int i = 0; i < 8; i++)
        #pragma unroll
        for (int j = 0; j < 8; j++) acc[i][j] = 0.f;

    const int lc = tid >> 1, lk4 = (tid & 1) * 4;
    const int lkk = tid >> 5, ln0 = (tid & 31) * 4;

    for (int d0 = 0; d0 < C_; d0 += 8) {
        {
            float4 v = *(const float4*)(p + lc * C_ + d0 + lk4);
            Ps[lk4 + 0][lc] = v.x; Ps[lk4 + 1][lc] = v.y;
            Ps[lk4 + 2][lc] = v.z; Ps[lk4 + 3][lc] = v.w;
        }
        {
            float4 v = *(const float4*)(q + (size_t)(d0 + lkk) * N_ + n0 + ln0);
            *(float4*)&Qs[lkk][ln0] = v;
        }
        __syncthreads();
        #pragma unroll
        for (int kk = 0; kk < 8; kk++) {
            float a[8], bb[8];
            float4 a0 = *(const float4*)&Ps[kk][tm * 8];
            float4 a1 = *(const float4*)&Ps[kk][tm * 8 + 4];
            float4 b0 = *(const float4*)&Qs[kk][tn * 8];
            float4 b1 = *(const float4*)&Qs[kk][tn * 8 + 4];
            a[0]=a0.x; a[1]=a0.y; a[2]=a0.z; a[3]=a0.w;
            a[4]=a1.x; a[5]=a1.y; a[6]=a1.z; a[7]=a1.w;
            bb[0]=b0.x; bb[1]=b0.y; bb[2]=b0.z; bb[3]=b0.w;
            bb[4]=b1.x; bb[5]=b1.y; bb[6]=b1.z; bb[7]=b1.w;
            #pragma unroll
            for (int i = 0; i < 8; i++)
                #pragma unroll
                for (int j = 0; j < 8; j++)
                    acc[i][j] = fmaf(a[i], bb[j], acc[i][j]);
        }
        __syncthreads();
    }

    const float g0 = gamma[0];
    #pragma unroll
    for (int i = 0; i < 8; i++) {
        const int c = tm * 8 + i;
        const size_t base = ((size_t)b * C_ + c) * N_ + n0 + tn * 8;
        #pragma unroll
        for (int j = 0; j < 8; j++)
            out[base + j] = g0 * acc[i][j] + g_y[base + j];
    }
}

// ===== launch ==============================================================
extern "C" void kernel_launch(void* const* d_in, const int* in_sizes, int n_in,
                              void* d_out, int out_size) {
    const float* x1       = (const float*)d_in[0];
    const float* x2       = (const float*)d_in[1];
    const float* se_w1    = (const float*)d_in[2];
    const float* se_w2    = (const float*)d_in[3];
    const float* conv_w   = (const float*)d_in[4];
    const float* bn_gamma = (const float*)d_in[5];
    const float* bn_beta  = (const float*)d_in[6];
    const float* bn_mean  = (const float*)d_in[7];
    const float* bn_var   = (const float*)d_in[8];
    const float* gamma    = (const float*)d_in[9];
    float* out = (float*)d_out;

    prep_wfrag_kernel<<<(288 * 8 * 2 * 32 + 255) / 256, 256>>>(conv_w);
    avgpool_kernel<<<B_ * C2_, 256>>>(x1, x2);
    se_mlp_kernel<<<1, C2_>>>(se_w1, se_w2);
    conv_mma_kernel<<<dim3(HW_, B_), 256>>>(x1, x2, bn_gamma, bn_beta, bn_mean, bn_var);
    sim_kernel<<<dim3(32, B_), 256>>>();
    softmax_kernel<<<dim3(C_, B_), 128>>>();
    feat_kernel<<<dim3(N_ / 128, B_), 256>>>(gamma, out);
}

// round 5
// speedup vs baseline: 1.7559x; 1.0548x over previous
#include <cuda_runtime.h>
#include <cstdint>
#include <math.h>

// Shapes: B=8, C=128, 2C=256, H=W=128, N=H*W=16384
#define B_ 8
#define C_ 128
#define C2_ 256
#define HW_ 128
#define N_ 16384
#define EPS_ 1e-5f

// ===================== tf32 helpers ========================================
__device__ __forceinline__ void split_tf32(float v, float& hf, float& lf) {
    uint32_t hb, lb;
    asm("cvt.rna.tf32.f32 %0, %1;" : "=r"(hb) : "f"(v));
    hf = __uint_as_float(hb);
    float lo = v - hf;
    asm("cvt.rna.tf32.f32 %0, %1;" : "=r"(lb) : "f"(lo));
    lf = __uint_as_float(lb);
}

__device__ __forceinline__ void mma1688(float4& d, const float4& a, float b0, float b1) {
    asm volatile(
        "mma.sync.aligned.m16n8k8.row.col.f32.tf32.tf32.f32 "
        "{%0,%1,%2,%3}, {%4,%5,%6,%7}, {%8,%9}, {%0,%1,%2,%3};"
        : "+f"(d.x), "+f"(d.y), "+f"(d.z), "+f"(d.w)
        : "r"(__float_as_uint(a.x)), "r"(__float_as_uint(a.y)),
          "r"(__float_as_uint(a.z)), "r"(__float_as_uint(a.w)),
          "r"(__float_as_uint(b0)), "r"(__float_as_uint(b1)));
}

// ===================== device scratch ======================================
__device__ __align__(16) float4 g_wfrag[288 * 8 * 2 * 32];
__device__ float g_avg[B_ * C2_];
__device__ float g_se[B_ * C2_];
__device__ __align__(16) float g_y[(size_t)B_ * C_ * N_];
__device__ __align__(16) float g_simp[(size_t)B_ * 32 * C_ * C_];
__device__ __align__(16) float g_p[B_ * C_ * C_];

// ===== 1. weight prep ======================================================
__global__ void prep_wfrag_kernel(const float* __restrict__ conv_w) {
    int idx = blockIdx.x * blockDim.x + threadIdx.x;
    if (idx >= 288 * 8 * 2 * 32) return;
    int lane = idx & 31;
    int s    = (idx >> 5) & 1;
    int mt   = (idx >> 6) & 7;
    int ks   = idx >> 9;
    int tap  = ks >> 5;
    int kc8  = ks & 31;
    int co = mt * 16 + (lane >> 2);
    int ci = kc8 * 8 + (lane & 3);
    float w00 = conv_w[((co    ) * C2_ + ci    ) * 9 + tap];
    float w10 = conv_w[((co + 8) * C2_ + ci    ) * 9 + tap];
    float w01 = conv_w[((co    ) * C2_ + ci + 4) * 9 + tap];
    float w11 = conv_w[((co + 8) * C2_ + ci + 4) * 9 + tap];
    float h00, l00, h10, l10, h01, l01, h11, l11;
    split_tf32(w00, h00, l00); split_tf32(w10, h10, l10);
    split_tf32(w01, h01, l01); split_tf32(w11, h11, l11);
    float4 v;
    if (s == 0) { v.x = h00; v.y = h10; v.z = h01; v.w = h11; }
    else        { v.x = l00; v.y = l10; v.z = l01; v.w = l11; }
    g_wfrag[idx] = v;
}

// ===== 2. global average pool ==============================================
__global__ void avgpool_kernel(const float* __restrict__ x1,
                               const float* __restrict__ x2) {
    int bc = blockIdx.x;
    int b = bc >> 8, c = bc & 255;
    const float* src = (c < C_) ? (x1 + ((size_t)(b * C_ + c)) * N_)
                                : (x2 + ((size_t)(b * C_ + (c - C_))) * N_);
    float s = 0.f;
    const float4* s4 = (const float4*)src;
    for (int i = threadIdx.x; i < N_ / 4; i += 256) {
        float4 v = s4[i];
        s += v.x + v.y + v.z + v.w;
    }
    for (int o = 16; o; o >>= 1) s += __shfl_down_sync(0xffffffffu, s, o);
    __shared__ float ws[8];
    int lane = threadIdx.x & 31, wid = threadIdx.x >> 5;
    if (lane == 0) ws[wid] = s;
    __syncthreads();
    if (threadIdx.x == 0) {
        float t = 0.f;
        #pragma unroll
        for (int i = 0; i < 8; i++) t += ws[i];
        g_avg[bc] = t * (1.f / (float)N_);
    }
}

// ===== 3. SE MLP ===========================================================
__global__ void se_mlp_kernel(const float* __restrict__ se_w1,
                              const float* __restrict__ se_w2) {
    __shared__ float avg_s[C2_];
    __shared__ float h_s[32];
    int tid = threadIdx.x;
    for (int b = 0; b < B_; b++) {
        avg_s[tid] = g_avg[b * C2_ + tid];
        __syncthreads();
        if (tid < 32) {
            float s = 0.f;
            #pragma unroll 8
            for (int k = 0; k < C2_; k++) s += avg_s[k] * se_w1[tid * C2_ + k];
            h_s[tid] = fmaxf(s, 0.f);
        }
        __syncthreads();
        {
            float s = 0.f;
            #pragma unroll
            for (int j = 0; j < 32; j++) s += h_s[j] * se_w2[tid * 32 + j];
            g_se[b * C2_ + tid] = 1.f / (1.f + expf(-s));
        }
        __syncthreads();
    }
}

// ===== 4. conv 3x3 via mma.sync tf32 (3-way split) + BN + ReLU =============
// EXACT round-3 kernel (proven correct at rel_err 2e-5)
#define BS_STRIDE 136

__global__ void __launch_bounds__(256, 2)
conv_mma_kernel(const float* __restrict__ x1, const float* __restrict__ x2,
                const float* __restrict__ bn_gamma, const float* __restrict__ bn_beta,
                const float* __restrict__ bn_mean, const float* __restrict__ bn_var) {
    __shared__ float Bs_hi[32 * BS_STRIDE];
    __shared__ float Bs_lo[32 * BS_STRIDE];

    const int tid = threadIdx.x;
    const int wid = tid >> 5, lane = tid & 31;
    const int warpM = wid >> 2, warpN = wid & 3;
    const int h = blockIdx.x, b = blockIdx.y;

    float4 acc[4][4];
    #pragma unroll
    for (int m = 0; m < 4; m++)
        #pragma unroll
        for (int n = 0; n < 4; n++) acc[m][n] = make_float4(0.f, 0.f, 0.f, 0.f);

    const int r = tid >> 3;
    const int wbase = tid & 7;

    const int tg = lane & 3;
    const int gp = lane >> 2;
    const int cbase = warpN * 32 + gp;

    for (int tap = 0; tap < 9; tap++) {
        const int hh = h + tap / 3 - 1;
        if (hh < 0 || hh >= HW_) continue;
        const int kw = tap % 3 - 1;

        for (int cib = 0; cib < 8; cib++) {
            __syncthreads();
            {
                const int ci = cib * 32 + r;
                const float se = g_se[b * C2_ + ci];
                const float* src = ((ci < C_) ? (x1 + ((size_t)(b * C_ + ci)) * N_)
                                              : (x2 + ((size_t)(b * C_ + ci - C_)) * N_))
                                   + (size_t)hh * HW_;
                #pragma unroll
                for (int e = 0; e < 16; e++) {
                    const int w = wbase + e * 8;
                    const int ws = w + kw;
                    float v = (ws >= 0 && ws < HW_) ? src[ws] * se : 0.f;
                    float hf, lf;
                    split_tf32(v, hf, lf);
                    Bs_hi[r * BS_STRIDE + w] = hf;
                    Bs_lo[r * BS_STRIDE + w] = lf;
                }
            }
            __syncthreads();

            #pragma unroll
            for (int j = 0; j < 4; j++) {
                const int ks = tap * 32 + cib * 4 + j;
                const int k0 = j * 8 + tg;

                float bh[4][2], bl[4][2];
                #pragma unroll
                for (int nt = 0; nt < 4; nt++) {
                    bh[nt][0] = Bs_hi[(k0    ) * BS_STRIDE + cbase + nt * 8];
                    bh[nt][1] = Bs_hi[(k0 + 4) * BS_STRIDE + cbase + nt * 8];
                    bl[nt][0] = Bs_lo[(k0    ) * BS_STRIDE + cbase + nt * 8];
                    bl[nt][1] = Bs_lo[(k0 + 4) * BS_STRIDE + cbase + nt * 8];
                }

                const size_t ofs = ((size_t)ks * 16 + warpM * 8) * 32 + lane;
                float4 ah[4];
                #pragma unroll
                for (int m = 0; m < 4; m++) ah[m] = g_wfrag[ofs + (size_t)(m * 2) * 32];

                #pragma unroll
                for (int m = 0; m < 4; m++)
                    #pragma unroll
                    for (int nt = 0; nt < 4; nt++)
                        mma1688(acc[m][nt], ah[m], bh[nt][0], bh[nt][1]);

                float4 al[4];
                #pragma unroll
                for (int m = 0; m < 4; m++) al[m] = g_wfrag[ofs + (size_t)(m * 2 + 1) * 32];

                #pragma unroll
                for (int m = 0; m < 4; m++)
                    #pragma unroll
                    for (int nt = 0; nt < 4; nt++)
                        mma1688(acc[m][nt], ah[m], bl[nt][0], bl[nt][1]);

                #pragma unroll
                for (int m = 0; m < 4; m++)
                    #pragma unroll
                    for (int nt = 0; nt < 4; nt++)
                        mma1688(acc[m][nt], al[m], bh[nt][0], bh[nt][1]);
            }
        }
    }

    #pragma unroll
    for (int m = 0; m < 4; m++) {
        const int co0 = warpM * 64 + m * 16 + gp;
        const int co1 = co0 + 8;
        const float inv0 = bn_gamma[co0] * rsqrtf(bn_var[co0] + EPS_);
        const float bia0 = bn_beta[co0] - bn_mean[co0] * inv0;
        const float inv1 = bn_gamma[co1] * rsqrtf(bn_var[co1] + EPS_);
        const float bia1 = bn_beta[co1] - bn_mean[co1] * inv1;
        #pragma unroll
        for (int nt = 0; nt < 4; nt++) {
            const int w = warpN * 32 + nt * 8 + tg * 2;
            float2 v0, v1;
            v0.x = fmaxf(acc[m][nt].x * inv0 + bia0, 0.f);
            v0.y = fmaxf(acc[m][nt].y * inv0 + bia0, 0.f);
            v1.x = fmaxf(acc[m][nt].z * inv1 + bia1, 0.f);
            v1.y = fmaxf(acc[m][nt].w * inv1 + bia1, 0.f);
            *(float2*)(g_y + ((size_t)(b * C_ + co0)) * N_ + (size_t)h * HW_ + w) = v0;
            *(float2*)(g_y + ((size_t)(b * C_ + co1)) * N_ + (size_t)h * HW_ + w) = v1;
        }
    }
}

// ===== 5. sim = Q Q^T via mma, split-K=32, double-buffered =================
#define SIMT 4608   // 128*36 floats per tile

__device__ __forceinline__ void sim_build(float* qh, float* ql,
                                          const float* __restrict__ q,
                                          int k0g, int c, int kseg) {
    const float* src = q + (size_t)c * N_ + k0g + kseg;
    float4 v[4];
    #pragma unroll
    for (int e = 0; e < 4; e++) v[e] = ((const float4*)src)[e];
    float* dh = qh + c * 36 + kseg;
    float* dl = ql + c * 36 + kseg;
    #pragma unroll
    for (int e = 0; e < 4; e++) {
        float hf, lf;
        split_tf32(v[e].x, hf, lf); dh[e * 4 + 0] = hf; dl[e * 4 + 0] = lf;
        split_tf32(v[e].y, hf, lf); dh[e * 4 + 1] = hf; dl[e * 4 + 1] = lf;
        split_tf32(v[e].z, hf, lf); dh[e * 4 + 2] = hf; dl[e * 4 + 2] = lf;
        split_tf32(v[e].w, hf, lf); dh[e * 4 + 3] = hf; dl[e * 4 + 3] = lf;
    }
}

__global__ void __launch_bounds__(256, 2)
sim_mma_kernel() {
    extern __shared__ float sms[];
    const int tid = threadIdx.x;
    const int wid = tid >> 5, lane = tid & 31;
    const int warpM = wid >> 2, warpN = wid & 3;
    const int tg = lane & 3, gp = lane >> 2;
    const int split = blockIdx.x, b = blockIdx.y;
    const float* q = g_y + (size_t)b * C_ * N_;
    const int k0g = split * 512;

    const int bc = tid >> 1, bks = (tid & 1) * 16;

    float4 acc[4][4];
    #pragma unroll
    for (int m = 0; m < 4; m++)
        #pragma unroll
        for (int n = 0; n < 4; n++) acc[m][n] = make_float4(0.f, 0.f, 0.f, 0.f);

    sim_build(sms, sms + SIMT, q, k0g, bc, bks);
    __syncthreads();

    for (int ch = 0; ch < 16; ch++) {
        const float* qh = sms + (ch & 1) * (2 * SIMT);
        const float* ql = qh + SIMT;
        #pragma unroll
        for (int j = 0; j < 4; j++) {
            const int k0 = j * 8 + tg;
            float4 ah[4], al[4];
            #pragma unroll
            for (int m = 0; m < 4; m++) {
                const int row = warpM * 64 + m * 16 + gp;
                ah[m].x = qh[row * 36 + k0];       ah[m].y = qh[(row + 8) * 36 + k0];
                ah[m].z = qh[row * 36 + k0 + 4];   ah[m].w = qh[(row + 8) * 36 + k0 + 4];
                al[m].x = ql[row * 36 + k0];       al[m].y = ql[(row + 8) * 36 + k0];
                al[m].z = ql[row * 36 + k0 + 4];   al[m].w = ql[(row + 8) * 36 + k0 + 4];
            }
            float bh[4][2], bl[4][2];
            #pragma unroll
            for (int nt = 0; nt < 4; nt++) {
                const int rb = warpN * 32 + nt * 8 + gp;
                bh[nt][0] = qh[rb * 36 + k0]; bh[nt][1] = qh[rb * 36 + k0 + 4];
                bl[nt][0] = ql[rb * 36 + k0]; bl[nt][1] = ql[rb * 36 + k0 + 4];
            }
            #pragma unroll
            for (int m = 0; m < 4; m++)
                #pragma unroll
                for (int nt = 0; nt < 4; nt++) {
                    mma1688(acc[m][nt], ah[m], bh[nt][0], bh[nt][1]);
                    mma1688(acc[m][nt], al[m], bh[nt][0], bh[nt][1]);
                    mma1688(acc[m][nt], ah[m], bl[nt][0], bl[nt][1]);
                }
        }
        if (ch + 1 < 16)
            sim_build(sms + ((ch + 1) & 1) * (2 * SIMT),
                      sms + ((ch + 1) & 1) * (2 * SIMT) + SIMT,
                      q, k0g + (ch + 1) * 32, bc, bks);
        __syncthreads();
    }

    float* dst = g_simp + (((size_t)(b * 32 + split)) * C_ * C_);
    #pragma unroll
    for (int m = 0; m < 4; m++) {
        const int c0 = warpM * 64 + m * 16 + gp;
        #pragma unroll
        for (int nt = 0; nt < 4; nt++) {
            const int d = warpN * 32 + nt * 8 + tg * 2;
            *(float2*)(dst + (size_t)c0 * C_ + d)       = make_float2(acc[m][nt].x, acc[m][nt].y);
            *(float2*)(dst + (size_t)(c0 + 8) * C_ + d) = make_float2(acc[m][nt].z, acc[m][nt].w);
        }
    }
}

// ===== 6. softmax(max - sim) == exp(min - sim)/sum =========================
__global__ void softmax_kernel() {
    const int c = blockIdx.x, b = blockIdx.y;
    const int d = threadIdx.x;
    float s = 0.f;
    #pragma unroll 8
    for (int sp = 0; sp < 32; sp++)
        s += g_simp[(((size_t)(b * 32 + sp)) * C_ + c) * C_ + d];

    __shared__ float red[128];
    red[d] = s;
    __syncthreads();
    for (int st = 64; st > 0; st >>= 1) {
        if (d < st) red[d] = fminf(red[d], red[d + st]);
        __syncthreads();
    }
    const float mn = red[0];
    __syncthreads();
    const float e = expf(mn - s);
    red[d] = e;
    __syncthreads();
    for (int st = 64; st > 0; st >>= 1) {
        if (d < st) red[d] += red[d + st];
        __syncthreads();
    }
    g_p[(b * C_ + c) * C_ + d] = e / red[0];
}

// ===== 7. feat = P @ Q via mma; out = gamma*feat + y =======================
#define FP_T 4608   // P tile 128*36
#define FQ_T 4352   // Q tile 32*136

__global__ void __launch_bounds__(256, 2)
feat_mma_kernel(const float* __restrict__ gamma, float* __restrict__ out) {
    extern __shared__ float fms[];
    float* Ph = fms;
    float* Pl = fms + FP_T;
    float* Qh = fms + 2 * FP_T;
    float* Ql = Qh + FQ_T;

    const int tid = threadIdx.x;
    const int wid = tid >> 5, lane = tid & 31;
    const int warpM = wid >> 2, warpN = wid & 3;
    const int tg = lane & 3, gp = lane >> 2;
    const int n0 = blockIdx.x * 128, b = blockIdx.y;

    const float* qsrc = g_y + (size_t)b * C_ * N_;
    const float* psrc = g_p + (size_t)b * C_ * C_;

    float4 acc[4][4];
    #pragma unroll
    for (int m = 0; m < 4; m++)
        #pragma unroll
        for (int n = 0; n < 4; n++) acc[m][n] = make_float4(0.f, 0.f, 0.f, 0.f);

    const int pc = tid >> 1, pds = (tid & 1) * 16;
    const int qr = tid >> 3, qcs = tid & 7;

    for (int ch = 0; ch < 4; ch++) {
        const int d0 = ch * 32;
        __syncthreads();
        {
            const float* src = psrc + (size_t)pc * C_ + d0 + pds;
            float4 v[4];
            #pragma unroll
            for (int e = 0; e < 4; e++) v[e] = ((const float4*)src)[e];
            float* dh = Ph + pc * 36 + pds;
            float* dl = Pl + pc * 36 + pds;
            #pragma unroll
            for (int e = 0; e < 4; e++) {
                float hf, lf;
                split_tf32(v[e].x, hf, lf); dh[e * 4 + 0] = hf; dl[e * 4 + 0] = lf;
                split_tf32(v[e].y, hf, lf); dh[e * 4 + 1] = hf; dl[e * 4 + 1] = lf;
                split_tf32(v[e].z, hf, lf); dh[e * 4 + 2] = hf; dl[e * 4 + 2] = lf;
                split_tf32(v[e].w, hf, lf); dh[e * 4 + 3] = hf; dl[e * 4 + 3] = lf;
            }
        }
        {
            const float* src = qsrc + (size_t)(d0 + qr) * N_ + n0 + qcs * 16;
            #pragma unroll
            for (int e = 0; e < 4; e++) {
                float4 v = ((const float4*)src)[e];
                float4 vh, vl;
                split_tf32(v.x, vh.x, vl.x); split_tf32(v.y, vh.y, vl.y);
                split_tf32(v.z, vh.z, vl.z); split_tf32(v.w, vh.w, vl.w);
                *(float4*)&Qh[qr * 136 + qcs * 16 + e * 4] = vh;
                *(float4*)&Ql[qr * 136 + qcs * 16 + e * 4] = vl;
            }
        }
        __syncthreads();

        #pragma unroll
        for (int j = 0; j < 4; j++) {
            const int k0 = j * 8 + tg;
            float4 ah[4], al[4];
            #pragma unroll
            for (int m = 0; m < 4; m++) {
                const int row = warpM * 64 + m * 16 + gp;
                ah[m].x = Ph[row * 36 + k0];       ah[m].y = Ph[(row + 8) * 36 + k0];
                ah[m].z = Ph[row * 36 + k0 + 4];   ah[m].w = Ph[(row + 8) * 36 + k0 + 4];
                al[m].x = Pl[row * 36 + k0];       al[m].y = Pl[(row + 8) * 36 + k0];
                al[m].z = Pl[row * 36 + k0 + 4];   al[m].w = Pl[(row + 8) * 36 + k0 + 4];
            }
            float bh[4][2], bl[4][2];
            #pragma unroll
            for (int nt = 0; nt < 4; nt++) {
                const int cb = warpN * 32 + nt * 8 + gp;
                bh[nt][0] = Qh[k0 * 136 + cb]; bh[nt][1] = Qh[(k0 + 4) * 136 + cb];
                bl[nt][0] = Ql[k0 * 136 + cb]; bl[nt][1] = Ql[(k0 + 4) * 136 + cb];
            }
            #pragma unroll
            for (int m = 0; m < 4; m++)
                #pragma unroll
                for (int nt = 0; nt < 4; nt++) {
                    mma1688(acc[m][nt], ah[m], bh[nt][0], bh[nt][1]);
                    mma1688(acc[m][nt], al[m], bh[nt][0], bh[nt][1]);
                    mma1688(acc[m][nt], ah[m], bl[nt][0], bl[nt][1]);
                }
        }
    }

    const float g0 = gamma[0];
    #pragma unroll
    for (int m = 0; m < 4; m++) {
        const int co0 = warpM * 64 + m * 16 + gp;
        const int co1 = co0 + 8;
        #pragma unroll
        for (int nt = 0; nt < 4; nt++) {
            const int w = warpN * 32 + nt * 8 + tg * 2;
            const size_t a0 = ((size_t)(b * C_ + co0)) * N_ + n0 + w;
            const size_t a1 = ((size_t)(b * C_ + co1)) * N_ + n0 + w;
            float2 y0 = *(const float2*)(g_y + a0);
            float2 y1 = *(const float2*)(g_y + a1);
            float2 o0, o1;
            o0.x = g0 * acc[m][nt].x + y0.x;  o0.y = g0 * acc[m][nt].y + y0.y;
            o1.x = g0 * acc[m][nt].z + y1.x;  o1.y = g0 * acc[m][nt].w + y1.y;
            *(float2*)(out + a0) = o0;
            *(float2*)(out + a1) = o1;
        }
    }
}

// ===== launch ==============================================================
extern "C" void kernel_launch(void* const* d_in, const int* in_sizes, int n_in,
                              void* d_out, int out_size) {
    const float* x1       = (const float*)d_in[0];
    const float* x2       = (const float*)d_in[1];
    const float* se_w1    = (const float*)d_in[2];
    const float* se_w2    = (const float*)d_in[3];
    const float* conv_w   = (const float*)d_in[4];
    const float* bn_gamma = (const float*)d_in[5];
    const float* bn_beta  = (const float*)d_in[6];
    const float* bn_mean  = (const float*)d_in[7];
    const float* bn_var   = (const float*)d_in[8];
    const float* gamma    = (const float*)d_in[9];
    float* out = (float*)d_out;

    const int sim_smem  = 4 * SIMT * 4;              // 73728
    const int feat_smem = (2 * FP_T + 2 * FQ_T) * 4; // 71680
    cudaFuncSetAttribute(sim_mma_kernel,  cudaFuncAttributeMaxDynamicSharedMemorySize, sim_smem);
    cudaFuncSetAttribute(feat_mma_kernel, cudaFuncAttributeMaxDynamicSharedMemorySize, feat_smem);

    prep_wfrag_kernel<<<(288 * 8 * 2 * 32 + 255) / 256, 256>>>(conv_w);
    avgpool_kernel<<<B_ * C2_, 256>>>(x1, x2);
    se_mlp_kernel<<<1, C2_>>>(se_w1, se_w2);
    conv_mma_kernel<<<dim3(HW_, B_), 256>>>(x1, x2, bn_gamma, bn_beta, bn_mean, bn_var);
    sim_mma_kernel<<<dim3(32, B_), 256, sim_smem>>>();
    softmax_kernel<<<dim3(C_, B_), 128>>>();
    feat_mma_kernel<<<dim3(N_ / 128, B_), 256, feat_smem>>>(gamma, out);
}

// round 6
// speedup vs baseline: 1.7681x; 1.0069x over previous
#include <cuda_runtime.h>
#include <cstdint>
#include <math.h>

// Shapes: B=8, C=128, 2C=256, H=W=128, N=H*W=16384
#define B_ 8
#define C_ 128
#define C2_ 256
#define HW_ 128
#define N_ 16384
#define EPS_ 1e-5f

// ===================== tf32 helpers ========================================
__device__ __forceinline__ void split_tf32(float v, float& hf, float& lf) {
    uint32_t hb, lb;
    asm("cvt.rna.tf32.f32 %0, %1;" : "=r"(hb) : "f"(v));
    hf = __uint_as_float(hb);
    float lo = v - hf;
    asm("cvt.rna.tf32.f32 %0, %1;" : "=r"(lb) : "f"(lo));
    lf = __uint_as_float(lb);
}

__device__ __forceinline__ void mma1688(float4& d, const float4& a, float b0, float b1) {
    asm volatile(
        "mma.sync.aligned.m16n8k8.row.col.f32.tf32.tf32.f32 "
        "{%0,%1,%2,%3}, {%4,%5,%6,%7}, {%8,%9}, {%0,%1,%2,%3};"
        : "+f"(d.x), "+f"(d.y), "+f"(d.z), "+f"(d.w)
        : "r"(__float_as_uint(a.x)), "r"(__float_as_uint(a.y)),
          "r"(__float_as_uint(a.z)), "r"(__float_as_uint(a.w)),
          "r"(__float_as_uint(b0)), "r"(__float_as_uint(b1)));
}

// ===================== device scratch ======================================
__device__ __align__(16) float4 g_wfrag[288 * 8 * 2 * 32];
__device__ float g_avg[B_ * C2_];
__device__ float g_se[B_ * C2_];
__device__ __align__(16) float g_y[(size_t)B_ * C_ * N_];
__device__ __align__(16) float g_simp[(size_t)B_ * 32 * C_ * C_];
__device__ __align__(16) float g_p[B_ * C_ * C_];

// ===== 1. weight prep ======================================================
__global__ void prep_wfrag_kernel(const float* __restrict__ conv_w) {
    int idx = blockIdx.x * blockDim.x + threadIdx.x;
    if (idx >= 288 * 8 * 2 * 32) return;
    int lane = idx & 31;
    int s    = (idx >> 5) & 1;
    int mt   = (idx >> 6) & 7;
    int ks   = idx >> 9;
    int tap  = ks >> 5;
    int kc8  = ks & 31;
    int co = mt * 16 + (lane >> 2);
    int ci = kc8 * 8 + (lane & 3);
    float w00 = conv_w[((co    ) * C2_ + ci    ) * 9 + tap];
    float w10 = conv_w[((co + 8) * C2_ + ci    ) * 9 + tap];
    float w01 = conv_w[((co    ) * C2_ + ci + 4) * 9 + tap];
    float w11 = conv_w[((co + 8) * C2_ + ci + 4) * 9 + tap];
    float h00, l00, h10, l10, h01, l01, h11, l11;
    split_tf32(w00, h00, l00); split_tf32(w10, h10, l10);
    split_tf32(w01, h01, l01); split_tf32(w11, h11, l11);
    float4 v;
    if (s == 0) { v.x = h00; v.y = h10; v.z = h01; v.w = h11; }
    else        { v.x = l00; v.y = l10; v.z = l01; v.w = l11; }
    g_wfrag[idx] = v;
}

// ===== 2. global average pool ==============================================
__global__ void avgpool_kernel(const float* __restrict__ x1,
                               const float* __restrict__ x2) {
    int bc = blockIdx.x;
    int b = bc >> 8, c = bc & 255;
    const float* src = (c < C_) ? (x1 + ((size_t)(b * C_ + c)) * N_)
                                : (x2 + ((size_t)(b * C_ + (c - C_))) * N_);
    float s = 0.f;
    const float4* s4 = (const float4*)src;
    for (int i = threadIdx.x; i < N_ / 4; i += 256) {
        float4 v = s4[i];
        s += v.x + v.y + v.z + v.w;
    }
    for (int o = 16; o; o >>= 1) s += __shfl_down_sync(0xffffffffu, s, o);
    __shared__ float ws[8];
    int lane = threadIdx.x & 31, wid = threadIdx.x >> 5;
    if (lane == 0) ws[wid] = s;
    __syncthreads();
    if (threadIdx.x == 0) {
        float t = 0.f;
        #pragma unroll
        for (int i = 0; i < 8; i++) t += ws[i];
        g_avg[bc] = t * (1.f / (float)N_);
    }
}

// ===== 3. SE MLP ===========================================================
__global__ void se_mlp_kernel(const float* __restrict__ se_w1,
                              const float* __restrict__ se_w2) {
    __shared__ float avg_s[C2_];
    __shared__ float h_s[32];
    int tid = threadIdx.x;
    for (int b = 0; b < B_; b++) {
        avg_s[tid] = g_avg[b * C2_ + tid];
        __syncthreads();
        if (tid < 32) {
            float s = 0.f;
            #pragma unroll 8
            for (int k = 0; k < C2_; k++) s += avg_s[k] * se_w1[tid * C2_ + k];
            h_s[tid] = fmaxf(s, 0.f);
        }
        __syncthreads();
        {
            float s = 0.f;
            #pragma unroll
            for (int j = 0; j < 32; j++) s += h_s[j] * se_w2[tid * 32 + j];
            g_se[b * C2_ + tid] = 1.f / (1.f + expf(-s));
        }
        __syncthreads();
    }
}

// ===== 4. conv 3x3 via mma.sync tf32 (3-way split) + BN + ReLU =============
// Round-3 build/MMA mappings, now double-buffered: one sync per K-chunk.
#define BS_STRIDE 136
#define CVTILE (32 * BS_STRIDE)   // 4352 floats per tile

// Build B tile for (tap, cib) into th/tl — EXACT round-3 mapping
__device__ __forceinline__ void conv_build(
    float* __restrict__ th, float* __restrict__ tl,
    const float* __restrict__ x1, const float* __restrict__ x2,
    int b, int h, int tap, int cib, int r, int wbase)
{
    const int hh = h + tap / 3 - 1;
    const int kw = tap % 3 - 1;
    const int ci = cib * 32 + r;
    const float se = g_se[b * C2_ + ci];
    const float* src = ((ci < C_) ? (x1 + ((size_t)(b * C_ + ci)) * N_)
                                  : (x2 + ((size_t)(b * C_ + ci - C_)) * N_))
                       + (size_t)hh * HW_;
    #pragma unroll
    for (int e = 0; e < 16; e++) {
        const int w = wbase + e * 8;
        const int ws = w + kw;
        float v = (ws >= 0 && ws < HW_) ? src[ws] * se : 0.f;
        float hf, lf;
        split_tf32(v, hf, lf);
        th[r * BS_STRIDE + w] = hf;
        tl[r * BS_STRIDE + w] = lf;
    }
}

__global__ void __launch_bounds__(256, 2)
conv_mma_kernel(const float* __restrict__ x1, const float* __restrict__ x2,
                const float* __restrict__ bn_gamma, const float* __restrict__ bn_beta,
                const float* __restrict__ bn_mean, const float* __restrict__ bn_var) {
    extern __shared__ float cvs[];   // [buf0_hi][buf0_lo][buf1_hi][buf1_lo]

    const int tid = threadIdx.x;
    const int wid = tid >> 5, lane = tid & 31;
    const int warpM = wid >> 2, warpN = wid & 3;
    const int h = blockIdx.x, b = blockIdx.y;

    float4 acc[4][4];
    #pragma unroll
    for (int m = 0; m < 4; m++)
        #pragma unroll
        for (int n = 0; n < 4; n++) acc[m][n] = make_float4(0.f, 0.f, 0.f, 0.f);

    const int r = tid >> 3;
    const int wbase = tid & 7;

    const int tg = lane & 3;
    const int gp = lane >> 2;
    const int cbase = warpN * 32 + gp;

    // valid taps (block-uniform)
    int vt[9], nv = 0;
    #pragma unroll
    for (int tap = 0; tap < 9; tap++) {
        const int hh = h + tap / 3 - 1;
        if (hh >= 0 && hh < HW_) vt[nv++] = tap;
    }
    const int nch = nv * 8;

    conv_build(cvs, cvs + CVTILE, x1, x2, b, h, vt[0], 0, r, wbase);
    __syncthreads();

    for (int q = 0; q < nch; q++) {
        const int tap = vt[q >> 3], cib = q & 7;
        const float* th = cvs + (q & 1) * (2 * CVTILE);
        const float* tl = th + CVTILE;

        #pragma unroll
        for (int j = 0; j < 4; j++) {
            const int ks = tap * 32 + cib * 4 + j;
            const int k0 = j * 8 + tg;

            float bh[4][2], bl[4][2];
            #pragma unroll
            for (int nt = 0; nt < 4; nt++) {
                bh[nt][0] = th[(k0    ) * BS_STRIDE + cbase + nt * 8];
                bh[nt][1] = th[(k0 + 4) * BS_STRIDE + cbase + nt * 8];
                bl[nt][0] = tl[(k0    ) * BS_STRIDE + cbase + nt * 8];
                bl[nt][1] = tl[(k0 + 4) * BS_STRIDE + cbase + nt * 8];
            }

            const size_t ofs = ((size_t)ks * 16 + warpM * 8) * 32 + lane;
            float4 ah[4];
            #pragma unroll
            for (int m = 0; m < 4; m++) ah[m] = g_wfrag[ofs + (size_t)(m * 2) * 32];

            #pragma unroll
            for (int m = 0; m < 4; m++)
                #pragma unroll
                for (int nt = 0; nt < 4; nt++)
                    mma1688(acc[m][nt], ah[m], bh[nt][0], bh[nt][1]);

            float4 al[4];
            #pragma unroll
            for (int m = 0; m < 4; m++) al[m] = g_wfrag[ofs + (size_t)(m * 2 + 1) * 32];

            #pragma unroll
            for (int m = 0; m < 4; m++)
                #pragma unroll
                for (int nt = 0; nt < 4; nt++)
                    mma1688(acc[m][nt], ah[m], bl[nt][0], bl[nt][1]);

            #pragma unroll
            for (int m = 0; m < 4; m++)
                #pragma unroll
                for (int nt = 0; nt < 4; nt++)
                    mma1688(acc[m][nt], al[m], bh[nt][0], bh[nt][1]);
        }

        if (q + 1 < nch) {
            const int q2 = q + 1;
            float* nh = cvs + (q2 & 1) * (2 * CVTILE);
            conv_build(nh, nh + CVTILE, x1, x2, b, h, vt[q2 >> 3], q2 & 7, r, wbase);
        }
        __syncthreads();
    }

    #pragma unroll
    for (int m = 0; m < 4; m++) {
        const int co0 = warpM * 64 + m * 16 + gp;
        const int co1 = co0 + 8;
        const float inv0 = bn_gamma[co0] * rsqrtf(bn_var[co0] + EPS_);
        const float bia0 = bn_beta[co0] - bn_mean[co0] * inv0;
        const float inv1 = bn_gamma[co1] * rsqrtf(bn_var[co1] + EPS_);
        const float bia1 = bn_beta[co1] - bn_mean[co1] * inv1;
        #pragma unroll
        for (int nt = 0; nt < 4; nt++) {
            const int w = warpN * 32 + nt * 8 + tg * 2;
            float2 v0, v1;
            v0.x = fmaxf(acc[m][nt].x * inv0 + bia0, 0.f);
            v0.y = fmaxf(acc[m][nt].y * inv0 + bia0, 0.f);
            v1.x = fmaxf(acc[m][nt].z * inv1 + bia1, 0.f);
            v1.y = fmaxf(acc[m][nt].w * inv1 + bia1, 0.f);
            *(float2*)(g_y + ((size_t)(b * C_ + co0)) * N_ + (size_t)h * HW_ + w) = v0;
            *(float2*)(g_y + ((size_t)(b * C_ + co1)) * N_ + (size_t)h * HW_ + w) = v1;
        }
    }
}

// ===== 5. sim = Q Q^T via mma, split-K=32, double-buffered =================
#define SIMT 4608   // 128*36 floats per tile

__device__ __forceinline__ void sim_build(float* qh, float* ql,
                                          const float* __restrict__ q,
                                          int k0g, int c, int kseg) {
    const float* src = q + (size_t)c * N_ + k0g + kseg;
    float4 v[4];
    #pragma unroll
    for (int e = 0; e < 4; e++) v[e] = ((const float4*)src)[e];
    float* dh = qh + c * 36 + kseg;
    float* dl = ql + c * 36 + kseg;
    #pragma unroll
    for (int e = 0; e < 4; e++) {
        float hf, lf;
        split_tf32(v[e].x, hf, lf); dh[e * 4 + 0] = hf; dl[e * 4 + 0] = lf;
        split_tf32(v[e].y, hf, lf); dh[e * 4 + 1] = hf; dl[e * 4 + 1] = lf;
        split_tf32(v[e].z, hf, lf); dh[e * 4 + 2] = hf; dl[e * 4 + 2] = lf;
        split_tf32(v[e].w, hf, lf); dh[e * 4 + 3] = hf; dl[e * 4 + 3] = lf;
    }
}

__global__ void __launch_bounds__(256, 2)
sim_mma_kernel() {
    extern __shared__ float sms[];
    const int tid = threadIdx.x;
    const int wid = tid >> 5, lane = tid & 31;
    const int warpM = wid >> 2, warpN = wid & 3;
    const int tg = lane & 3, gp = lane >> 2;
    const int split = blockIdx.x, b = blockIdx.y;
    const float* q = g_y + (size_t)b * C_ * N_;
    const int k0g = split * 512;

    const int bc = tid >> 1, bks = (tid & 1) * 16;

    float4 acc[4][4];
    #pragma unroll
    for (int m = 0; m < 4; m++)
        #pragma unroll
        for (int n = 0; n < 4; n++) acc[m][n] = make_float4(0.f, 0.f, 0.f, 0.f);

    sim_build(sms, sms + SIMT, q, k0g, bc, bks);
    __syncthreads();

    for (int ch = 0; ch < 16; ch++) {
        const float* qh = sms + (ch & 1) * (2 * SIMT);
        const float* ql = qh + SIMT;
        #pragma unroll
        for (int j = 0; j < 4; j++) {
            const int k0 = j * 8 + tg;
            float4 ah[4], al[4];
            #pragma unroll
            for (int m = 0; m < 4; m++) {
                const int row = warpM * 64 + m * 16 + gp;
                ah[m].x = qh[row * 36 + k0];       ah[m].y = qh[(row + 8) * 36 + k0];
                ah[m].z = qh[row * 36 + k0 + 4];   ah[m].w = qh[(row + 8) * 36 + k0 + 4];
                al[m].x = ql[row * 36 + k0];       al[m].y = ql[(row + 8) * 36 + k0];
                al[m].z = ql[row * 36 + k0 + 4];   al[m].w = ql[(row + 8) * 36 + k0 + 4];
            }
            float bh[4][2], bl[4][2];
            #pragma unroll
            for (int nt = 0; nt < 4; nt++) {
                const int rb = warpN * 32 + nt * 8 + gp;
                bh[nt][0] = qh[rb * 36 + k0]; bh[nt][1] = qh[rb * 36 + k0 + 4];
                bl[nt][0] = ql[rb * 36 + k0]; bl[nt][1] = ql[rb * 36 + k0 + 4];
            }
            #pragma unroll
            for (int m = 0; m < 4; m++)
                #pragma unroll
                for (int nt = 0; nt < 4; nt++) {
                    mma1688(acc[m][nt], ah[m], bh[nt][0], bh[nt][1]);
                    mma1688(acc[m][nt], al[m], bh[nt][0], bh[nt][1]);
                    mma1688(acc[m][nt], ah[m], bl[nt][0], bl[nt][1]);
                }
        }
        if (ch + 1 < 16)
            sim_build(sms + ((ch + 1) & 1) * (2 * SIMT),
                      sms + ((ch + 1) & 1) * (2 * SIMT) + SIMT,
                      q, k0g + (ch + 1) * 32, bc, bks);
        __syncthreads();
    }

    float* dst = g_simp + (((size_t)(b * 32 + split)) * C_ * C_);
    #pragma unroll
    for (int m = 0; m < 4; m++) {
        const int c0 = warpM * 64 + m * 16 + gp;
        #pragma unroll
        for (int nt = 0; nt < 4; nt++) {
            const int d = warpN * 32 + nt * 8 + tg * 2;
            *(float2*)(dst + (size_t)c0 * C_ + d)       = make_float2(acc[m][nt].x, acc[m][nt].y);
            *(float2*)(dst + (size_t)(c0 + 8) * C_ + d) = make_float2(acc[m][nt].z, acc[m][nt].w);
        }
    }
}

// ===== 6. softmax(max - sim) == exp(min - sim)/sum =========================
__global__ void softmax_kernel() {
    const int c = blockIdx.x, b = blockIdx.y;
    const int d = threadIdx.x;
    float s = 0.f;
    #pragma unroll 8
    for (int sp = 0; sp < 32; sp++)
        s += g_simp[(((size_t)(b * 32 + sp)) * C_ + c) * C_ + d];

    __shared__ float red[128];
    red[d] = s;
    __syncthreads();
    for (int st = 64; st > 0; st >>= 1) {
        if (d < st) red[d] = fminf(red[d], red[d + st]);
        __syncthreads();
    }
    const float mn = red[0];
    __syncthreads();
    const float e = expf(mn - s);
    red[d] = e;
    __syncthreads();
    for (int st = 64; st > 0; st >>= 1) {
        if (d < st) red[d] += red[d + st];
        __syncthreads();
    }
    g_p[(b * C_ + c) * C_ + d] = e / red[0];
}

// ===== 7. feat = P @ Q via mma; out = gamma*feat + y =======================
#define FP_T 4608   // P tile 128*36
#define FQ_T 4352   // Q tile 32*136

__global__ void __launch_bounds__(256, 2)
feat_mma_kernel(const float* __restrict__ gamma, float* __restrict__ out) {
    extern __shared__ float fms[];
    float* Ph = fms;
    float* Pl = fms + FP_T;
    float* Qh = fms + 2 * FP_T;
    float* Ql = Qh + FQ_T;

    const int tid = threadIdx.x;
    const int wid = tid >> 5, lane = tid & 31;
    const int warpM = wid >> 2, warpN = wid & 3;
    const int tg = lane & 3, gp = lane >> 2;
    const int n0 = blockIdx.x * 128, b = blockIdx.y;

    const float* qsrc = g_y + (size_t)b * C_ * N_;
    const float* psrc = g_p + (size_t)b * C_ * C_;

    float4 acc[4][4];
    #pragma unroll
    for (int m = 0; m < 4; m++)
        #pragma unroll
        for (int n = 0; n < 4; n++) acc[m][n] = make_float4(0.f, 0.f, 0.f, 0.f);

    const int pc = tid >> 1, pds = (tid & 1) * 16;
    const int qr = tid >> 3, qcs = tid & 7;

    for (int ch = 0; ch < 4; ch++) {
        const int d0 = ch * 32;
        __syncthreads();
        {
            const float* src = psrc + (size_t)pc * C_ + d0 + pds;
            float4 v[4];
            #pragma unroll
            for (int e = 0; e < 4; e++) v[e] = ((const float4*)src)[e];
            float* dh = Ph + pc * 36 + pds;
            float* dl = Pl + pc * 36 + pds;
            #pragma unroll
            for (int e = 0; e < 4; e++) {
                float hf, lf;
                split_tf32(v[e].x, hf, lf); dh[e * 4 + 0] = hf; dl[e * 4 + 0] = lf;
                split_tf32(v[e].y, hf, lf); dh[e * 4 + 1] = hf; dl[e * 4 + 1] = lf;
                split_tf32(v[e].z, hf, lf); dh[e * 4 + 2] = hf; dl[e * 4 + 2] = lf;
                split_tf32(v[e].w, hf, lf); dh[e * 4 + 3] = hf; dl[e * 4 + 3] = lf;
            }
        }
        {
            const float* src = qsrc + (size_t)(d0 + qr) * N_ + n0 + qcs * 16;
            #pragma unroll
            for (int e = 0; e < 4; e++) {
                float4 v = ((const float4*)src)[e];
                float4 vh, vl;
                split_tf32(v.x, vh.x, vl.x); split_tf32(v.y, vh.y, vl.y);
                split_tf32(v.z, vh.z, vl.z); split_tf32(v.w, vh.w, vl.w);
                *(float4*)&Qh[qr * 136 + qcs * 16 + e * 4] = vh;
                *(float4*)&Ql[qr * 136 + qcs * 16 + e * 4] = vl;
            }
        }
        __syncthreads();

        #pragma unroll
        for (int j = 0; j < 4; j++) {
            const int k0 = j * 8 + tg;
            float4 ah[4], al[4];
            #pragma unroll
            for (int m = 0; m < 4; m++) {
                const int row = warpM * 64 + m * 16 + gp;
                ah[m].x = Ph[row * 36 + k0];       ah[m].y = Ph[(row + 8) * 36 + k0];
                ah[m].z = Ph[row * 36 + k0 + 4];   ah[m].w = Ph[(row + 8) * 36 + k0 + 4];
                al[m].x = Pl[row * 36 + k0];       al[m].y = Pl[(row + 8) * 36 + k0];
                al[m].z = Pl[row * 36 + k0 + 4];   al[m].w = Pl[(row + 8) * 36 + k0 + 4];
            }
            float bh[4][2], bl[4][2];
            #pragma unroll
            for (int nt = 0; nt < 4; nt++) {
                const int cb = warpN * 32 + nt * 8 + gp;
                bh[nt][0] = Qh[k0 * 136 + cb]; bh[nt][1] = Qh[(k0 + 4) * 136 + cb];
                bl[nt][0] = Ql[k0 * 136 + cb]; bl[nt][1] = Ql[(k0 + 4) * 136 + cb];
            }
            #pragma unroll
            for (int m = 0; m < 4; m++)
                #pragma unroll
                for (int nt = 0; nt < 4; nt++) {
                    mma1688(acc[m][nt], ah[m], bh[nt][0], bh[nt][1]);
                    mma1688(acc[m][nt], al[m], bh[nt][0], bh[nt][1]);
                    mma1688(acc[m][nt], ah[m], bl[nt][0], bl[nt][1]);
                }
        }
    }

    const float g0 = gamma[0];
    #pragma unroll
    for (int m = 0; m < 4; m++) {
        const int co0 = warpM * 64 + m * 16 + gp;
        const int co1 = co0 + 8;
        #pragma unroll
        for (int nt = 0; nt < 4; nt++) {
            const int w = warpN * 32 + nt * 8 + tg * 2;
            const size_t a0 = ((size_t)(b * C_ + co0)) * N_ + n0 + w;
            const size_t a1 = ((size_t)(b * C_ + co1)) * N_ + n0 + w;
            float2 y0 = *(const float2*)(g_y + a0);
            float2 y1 = *(const float2*)(g_y + a1);
            float2 o0, o1;
            o0.x = g0 * acc[m][nt].x + y0.x;  o0.y = g0 * acc[m][nt].y + y0.y;
            o1.x = g0 * acc[m][nt].z + y1.x;  o1.y = g0 * acc[m][nt].w + y1.y;
            *(float2*)(out + a0) = o0;
            *(float2*)(out + a1) = o1;
        }
    }
}

// ===== launch ==============================================================
extern "C" void kernel_launch(void* const* d_in, const int* in_sizes, int n_in,
                              void* d_out, int out_size) {
    const float* x1       = (const float*)d_in[0];
    const float* x2       = (const float*)d_in[1];
    const float* se_w1    = (const float*)d_in[2];
    const float* se_w2    = (const float*)d_in[3];
    const float* conv_w   = (const float*)d_in[4];
    const float* bn_gamma = (const float*)d_in[5];
    const float* bn_beta  = (const float*)d_in[6];
    const float* bn_mean  = (const float*)d_in[7];
    const float* bn_var   = (const float*)d_in[8];
    const float* gamma    = (const float*)d_in[9];
    float* out = (float*)d_out;

    const int cv_smem   = 4 * CVTILE * 4;            // 69632
    const int sim_smem  = 4 * SIMT * 4;              // 73728
    const int feat_smem = (2 * FP_T + 2 * FQ_T) * 4; // 71680
    cudaFuncSetAttribute(conv_mma_kernel, cudaFuncAttributeMaxDynamicSharedMemorySize, cv_smem);
    cudaFuncSetAttribute(sim_mma_kernel,  cudaFuncAttributeMaxDynamicSharedMemorySize, sim_smem);
    cudaFuncSetAttribute(feat_mma_kernel, cudaFuncAttributeMaxDynamicSharedMemorySize, feat_smem);

    prep_wfrag_kernel<<<(288 * 8 * 2 * 32 + 255) / 256, 256>>>(conv_w);
    avgpool_kernel<<<B_ * C2_, 256>>>(x1, x2);
    se_mlp_kernel<<<1, C2_>>>(se_w1, se_w2);
    conv_mma_kernel<<<dim3(HW_, B_), 256, cv_smem>>>(x1, x2, bn_gamma, bn_beta, bn_mean, bn_var);
    sim_mma_kernel<<<dim3(32, B_), 256, sim_smem>>>();
    softmax_kernel<<<dim3(C_, B_), 128>>>();
    feat_mma_kernel<<<dim3(N_ / 128, B_), 256, feat_smem>>>(gamma, out);
}

// round 7
// speedup vs baseline: 2.2582x; 1.2772x over previous
#include <cuda_runtime.h>
#include <cuda_fp16.h>
#include <cstdint>
#include <math.h>

// Shapes: B=8, C=128, 2C=256, H=W=128, N=H*W=16384
#define B_ 8
#define C_ 128
#define C2_ 256
#define HW_ 128
#define N_ 16384
#define EPS_ 1e-5f

// ===================== fp16 split helpers ==================================
__device__ __forceinline__ void split_h(float v, __half& h, __half& l) {
    h = __float2half_rn(v);
    l = __float2half_rn(v - __half2float(h));
}
__device__ __forceinline__ uint32_t pack2(__half a, __half b) {
    return (uint32_t)__half_as_ushort(a) | ((uint32_t)__half_as_ushort(b) << 16);
}
__device__ __forceinline__ void mma16816(float4& d, uint32_t a0, uint32_t a1,
                                         uint32_t a2, uint32_t a3,
                                         uint32_t b0, uint32_t b1) {
    asm volatile(
        "mma.sync.aligned.m16n8k16.row.col.f32.f16.f16.f32 "
        "{%0,%1,%2,%3}, {%4,%5,%6,%7}, {%8,%9}, {%0,%1,%2,%3};"
        : "+f"(d.x), "+f"(d.y), "+f"(d.z), "+f"(d.w)
        : "r"(a0), "r"(a1), "r"(a2), "r"(a3), "r"(b0), "r"(b1));
}

// ===================== device scratch ======================================
// A fragments: idx = ((ks2*8 + mt)*2 + s)*32 + lane, ks2 = (tap*8+cib)*2+j2
__device__ __align__(16) uint4 g_wf16[144 * 8 * 2 * 32];
__device__ float g_avg[B_ * C2_];
__device__ float g_se[B_ * C2_];
__device__ __align__(16) float g_y[(size_t)B_ * C_ * N_];
__device__ __align__(16) float g_simp[(size_t)B_ * 32 * C_ * C_];
__device__ __align__(16) float g_p[B_ * C_ * C_];

// ===== 1. weight prep: conv_w [co][ci][tap] -> fp16 k16 fragments ==========
__global__ void prep_wf16_kernel(const float* __restrict__ conv_w) {
    int idx = blockIdx.x * blockDim.x + threadIdx.x;
    if (idx >= 144 * 8 * 2 * 32) return;
    int lane = idx & 31;
    int s    = (idx >> 5) & 1;
    int mt   = (idx >> 6) & 7;
    int ks2  = idx >> 9;                 // 0..143
    int j2   = ks2 & 1;
    int cib  = (ks2 >> 1) & 7;
    int tap  = ks2 >> 4;
    int tg = lane & 3, gp = lane >> 2;
    int co  = mt * 16 + gp;
    int ci0 = cib * 32 + j2 * 16;

    float w[8];
    // a0: (co, ci0+2tg, +1); a1: (co+8, same); a2: (co, ci0+2tg+8, +9); a3: (co+8, same)
    w[0] = conv_w[((co    ) * C2_ + ci0 + 2 * tg    ) * 9 + tap];
    w[1] = conv_w[((co    ) * C2_ + ci0 + 2 * tg + 1) * 9 + tap];
    w[2] = conv_w[((co + 8) * C2_ + ci0 + 2 * tg    ) * 9 + tap];
    w[3] = conv_w[((co + 8) * C2_ + ci0 + 2 * tg + 1) * 9 + tap];
    w[4] = conv_w[((co    ) * C2_ + ci0 + 2 * tg + 8) * 9 + tap];
    w[5] = conv_w[((co    ) * C2_ + ci0 + 2 * tg + 9) * 9 + tap];
    w[6] = conv_w[((co + 8) * C2_ + ci0 + 2 * tg + 8) * 9 + tap];
    w[7] = conv_w[((co + 8) * C2_ + ci0 + 2 * tg + 9) * 9 + tap];

    __half h[8], l[8];
    #pragma unroll
    for (int i = 0; i < 8; i++) split_h(w[i], h[i], l[i]);

    uint4 v;
    if (s == 0) {
        v.x = pack2(h[0], h[1]); v.y = pack2(h[2], h[3]);
        v.z = pack2(h[4], h[5]); v.w = pack2(h[6], h[7]);
    } else {
        v.x = pack2(l[0], l[1]); v.y = pack2(l[2], l[3]);
        v.z = pack2(l[4], l[5]); v.w = pack2(l[6], l[7]);
    }
    g_wf16[idx] = v;
}

// ===== 2. global average pool ==============================================
__global__ void avgpool_kernel(const float* __restrict__ x1,
                               const float* __restrict__ x2) {
    int bc = blockIdx.x;
    int b = bc >> 8, c = bc & 255;
    const float* src = (c < C_) ? (x1 + ((size_t)(b * C_ + c)) * N_)
                                : (x2 + ((size_t)(b * C_ + (c - C_))) * N_);
    float s = 0.f;
    const float4* s4 = (const float4*)src;
    for (int i = threadIdx.x; i < N_ / 4; i += 256) {
        float4 v = s4[i];
        s += v.x + v.y + v.z + v.w;
    }
    for (int o = 16; o; o >>= 1) s += __shfl_down_sync(0xffffffffu, s, o);
    __shared__ float ws[8];
    int lane = threadIdx.x & 31, wid = threadIdx.x >> 5;
    if (lane == 0) ws[wid] = s;
    __syncthreads();
    if (threadIdx.x == 0) {
        float t = 0.f;
        #pragma unroll
        for (int i = 0; i < 8; i++) t += ws[i];
        g_avg[bc] = t * (1.f / (float)N_);
    }
}

// ===== 3. SE MLP ===========================================================
__global__ void se_mlp_kernel(const float* __restrict__ se_w1,
                              const float* __restrict__ se_w2) {
    __shared__ float avg_s[C2_];
    __shared__ float h_s[32];
    int tid = threadIdx.x;
    for (int b = 0; b < B_; b++) {
        avg_s[tid] = g_avg[b * C2_ + tid];
        __syncthreads();
        if (tid < 32) {
            float s = 0.f;
            #pragma unroll 8
            for (int k = 0; k < C2_; k++) s += avg_s[k] * se_w1[tid * C2_ + k];
            h_s[tid] = fmaxf(s, 0.f);
        }
        __syncthreads();
        {
            float s = 0.f;
            #pragma unroll
            for (int j = 0; j < 32; j++) s += h_s[j] * se_w2[tid * 32 + j];
            g_se[b * C2_ + tid] = 1.f / (1.f + expf(-s));
        }
        __syncthreads();
    }
}

// ===== 4. conv 3x3 via mma.sync fp16 k16 (3-term split) + BN + ReLU ========
// B tile: k2 pairs (ci, ci+1) packed in half2; [k2=16][w=128] stride 136 u32.
#define CB_STR 136
#define CB_TILE (16 * CB_STR)   // 2176 u32 per tile

__device__ __forceinline__ void conv_build16(
    uint32_t* __restrict__ th, uint32_t* __restrict__ tl,
    const float* __restrict__ x1, const float* __restrict__ x2,
    int b, int h, int tap, int cib, int k2, int wseg)
{
    const int hh = h + tap / 3 - 1;
    const int kw = tap % 3 - 1;
    const int ci0 = cib * 32 + 2 * k2;
    const float se0 = g_se[b * C2_ + ci0];
    const float se1 = g_se[b * C2_ + ci0 + 1];
    const float* s0 = ((ci0 < C_) ? (x1 + ((size_t)(b * C_ + ci0)) * N_)
                                  : (x2 + ((size_t)(b * C_ + ci0 - C_)) * N_))
                      + (size_t)hh * HW_;
    const int ci1 = ci0 + 1;
    const float* s1 = ((ci1 < C_) ? (x1 + ((size_t)(b * C_ + ci1)) * N_)
                                  : (x2 + ((size_t)(b * C_ + ci1 - C_)) * N_))
                      + (size_t)hh * HW_;
    #pragma unroll
    for (int e = 0; e < 8; e++) {
        const int w = wseg + e;
        const int ws = w + kw;
        const bool ok = (ws >= 0 && ws < HW_);
        float v0 = ok ? s0[ws] * se0 : 0.f;
        float v1 = ok ? s1[ws] * se1 : 0.f;
        __half h0, l0, h1, l1;
        split_h(v0, h0, l0);
        split_h(v1, h1, l1);
        th[k2 * CB_STR + w] = pack2(h0, h1);
        tl[k2 * CB_STR + w] = pack2(l0, l1);
    }
}

__global__ void __launch_bounds__(256, 2)
conv_mma_kernel(const float* __restrict__ x1, const float* __restrict__ x2,
                const float* __restrict__ bn_gamma, const float* __restrict__ bn_beta,
                const float* __restrict__ bn_mean, const float* __restrict__ bn_var) {
    extern __shared__ uint32_t cvsu[];   // [buf0_hi][buf0_lo][buf1_hi][buf1_lo]

    const int tid = threadIdx.x;
    const int wid = tid >> 5, lane = tid & 31;
    const int warpM = wid >> 2, warpN = wid & 3;
    const int h = blockIdx.x, b = blockIdx.y;

    float4 acc[4][4];
    #pragma unroll
    for (int m = 0; m < 4; m++)
        #pragma unroll
        for (int n = 0; n < 4; n++) acc[m][n] = make_float4(0.f, 0.f, 0.f, 0.f);

    const int bk2 = tid >> 4;           // builder k2 0..15
    const int bws = (tid & 15) * 8;     // builder w segment

    const int tg = lane & 3;
    const int gp = lane >> 2;
    const int cbase = warpN * 32 + gp;

    int vt[9], nv = 0;
    #pragma unroll
    for (int tap = 0; tap < 9; tap++) {
        const int hh = h + tap / 3 - 1;
        if (hh >= 0 && hh < HW_) vt[nv++] = tap;
    }
    const int nch = nv * 8;

    conv_build16(cvsu, cvsu + CB_TILE, x1, x2, b, h, vt[0], 0, bk2, bws);
    __syncthreads();

    for (int q = 0; q < nch; q++) {
        const int tap = vt[q >> 3], cib = q & 7;
        const uint32_t* th = cvsu + (q & 1) * (2 * CB_TILE);
        const uint32_t* tl = th + CB_TILE;

        #pragma unroll
        for (int j2 = 0; j2 < 2; j2++) {
            const int ks2 = (tap * 8 + cib) * 2 + j2;
            const int k2a = j2 * 8 + tg;

            uint32_t bh0[4], bh1[4], bl0[4], bl1[4];
            #pragma unroll
            for (int nt = 0; nt < 4; nt++) {
                bh0[nt] = th[(k2a    ) * CB_STR + cbase + nt * 8];
                bh1[nt] = th[(k2a + 4) * CB_STR + cbase + nt * 8];
                bl0[nt] = tl[(k2a    ) * CB_STR + cbase + nt * 8];
                bl1[nt] = tl[(k2a + 4) * CB_STR + cbase + nt * 8];
            }

            uint4 ah[4];
            #pragma unroll
            for (int m = 0; m < 4; m++)
                ah[m] = g_wf16[((size_t)(ks2 * 8 + warpM * 4 + m) * 2) * 32 + lane];

            #pragma unroll
            for (int m = 0; m < 4; m++)
                #pragma unroll
                for (int nt = 0; nt < 4; nt++)
                    mma16816(acc[m][nt], ah[m].x, ah[m].y, ah[m].z, ah[m].w, bh0[nt], bh1[nt]);

            uint4 al[4];
            #pragma unroll
            for (int m = 0; m < 4; m++)
                al[m] = g_wf16[((size_t)(ks2 * 8 + warpM * 4 + m) * 2 + 1) * 32 + lane];

            #pragma unroll
            for (int m = 0; m < 4; m++)
                #pragma unroll
                for (int nt = 0; nt < 4; nt++)
                    mma16816(acc[m][nt], ah[m].x, ah[m].y, ah[m].z, ah[m].w, bl0[nt], bl1[nt]);

            #pragma unroll
            for (int m = 0; m < 4; m++)
                #pragma unroll
                for (int nt = 0; nt < 4; nt++)
                    mma16816(acc[m][nt], al[m].x, al[m].y, al[m].z, al[m].w, bh0[nt], bh1[nt]);
        }

        if (q + 1 < nch) {
            const int q2 = q + 1;
            uint32_t* nh = cvsu + (q2 & 1) * (2 * CB_TILE);
            conv_build16(nh, nh + CB_TILE, x1, x2, b, h, vt[q2 >> 3], q2 & 7, bk2, bws);
        }
        __syncthreads();
    }

    #pragma unroll
    for (int m = 0; m < 4; m++) {
        const int co0 = warpM * 64 + m * 16 + gp;
        const int co1 = co0 + 8;
        const float inv0 = bn_gamma[co0] * rsqrtf(bn_var[co0] + EPS_);
        const float bia0 = bn_beta[co0] - bn_mean[co0] * inv0;
        const float inv1 = bn_gamma[co1] * rsqrtf(bn_var[co1] + EPS_);
        const float bia1 = bn_beta[co1] - bn_mean[co1] * inv1;
        #pragma unroll
        for (int nt = 0; nt < 4; nt++) {
            const int w = warpN * 32 + nt * 8 + tg * 2;
            float2 v0, v1;
            v0.x = fmaxf(acc[m][nt].x * inv0 + bia0, 0.f);
            v0.y = fmaxf(acc[m][nt].y * inv0 + bia0, 0.f);
            v1.x = fmaxf(acc[m][nt].z * inv1 + bia1, 0.f);
            v1.y = fmaxf(acc[m][nt].w * inv1 + bia1, 0.f);
            *(float2*)(g_y + ((size_t)(b * C_ + co0)) * N_ + (size_t)h * HW_ + w) = v0;
            *(float2*)(g_y + ((size_t)(b * C_ + co1)) * N_ + (size_t)h * HW_ + w) = v1;
        }
    }
}

// ===== 5. sim = Q Q^T via fp16 mma, split-K=32, double-buffered ============
// Tile: [c=128][k2=16] stride 20 u32 (half2 pairs over k).
#define SQ_STR 20
#define SQ_TILE (128 * SQ_STR)   // 2560 u32 per tile

__device__ __forceinline__ void sim_build16(uint32_t* __restrict__ qh,
                                            uint32_t* __restrict__ ql,
                                            const float* __restrict__ q,
                                            int kbase, int c, int k2b) {
    const float* src = q + (size_t)c * N_ + kbase + 2 * k2b;
    #pragma unroll
    for (int e = 0; e < 8; e++) {
        float2 v = *(const float2*)(src + 2 * e);
        __half h0, l0, h1, l1;
        split_h(v.x, h0, l0);
        split_h(v.y, h1, l1);
        qh[c * SQ_STR + k2b + e] = pack2(h0, h1);
        ql[c * SQ_STR + k2b + e] = pack2(l0, l1);
    }
}

__global__ void __launch_bounds__(256, 2)
sim_mma_kernel() {
    extern __shared__ uint32_t smsu[];
    const int tid = threadIdx.x;
    const int wid = tid >> 5, lane = tid & 31;
    const int warpM = wid >> 2, warpN = wid & 3;
    const int tg = lane & 3, gp = lane >> 2;
    const int split = blockIdx.x, b = blockIdx.y;
    const float* q = g_y + (size_t)b * C_ * N_;
    const int k0g = split * 512;

    const int bc = tid >> 1, bk2 = (tid & 1) * 8;

    float4 acc[4][4];
    #pragma unroll
    for (int m = 0; m < 4; m++)
        #pragma unroll
        for (int n = 0; n < 4; n++) acc[m][n] = make_float4(0.f, 0.f, 0.f, 0.f);

    sim_build16(smsu, smsu + SQ_TILE, q, k0g, bc, bk2);
    __syncthreads();

    for (int ch = 0; ch < 16; ch++) {
        const uint32_t* qh = smsu + (ch & 1) * (2 * SQ_TILE);
        const uint32_t* ql = qh + SQ_TILE;

        #pragma unroll
        for (int j2 = 0; j2 < 2; j2++) {
            const int k2a = j2 * 8 + tg;
            uint32_t ah[4][4], al[4][4];
            #pragma unroll
            for (int m = 0; m < 4; m++) {
                const int row = warpM * 64 + m * 16 + gp;
                ah[m][0] = qh[row * SQ_STR + k2a];
                ah[m][1] = qh[(row + 8) * SQ_STR + k2a];
                ah[m][2] = qh[row * SQ_STR + k2a + 4];
                ah[m][3] = qh[(row + 8) * SQ_STR + k2a + 4];
                al[m][0] = ql[row * SQ_STR + k2a];
                al[m][1] = ql[(row + 8) * SQ_STR + k2a];
                al[m][2] = ql[row * SQ_STR + k2a + 4];
                al[m][3] = ql[(row + 8) * SQ_STR + k2a + 4];
            }
            uint32_t bh0[4], bh1[4], bl0[4], bl1[4];
            #pragma unroll
            for (int nt = 0; nt < 4; nt++) {
                const int rb = warpN * 32 + nt * 8 + gp;
                bh0[nt] = qh[rb * SQ_STR + k2a];
                bh1[nt] = qh[rb * SQ_STR + k2a + 4];
                bl0[nt] = ql[rb * SQ_STR + k2a];
                bl1[nt] = ql[rb * SQ_STR + k2a + 4];
            }
            #pragma unroll
            for (int m = 0; m < 4; m++)
                #pragma unroll
                for (int nt = 0; nt < 4; nt++) {
                    mma16816(acc[m][nt], ah[m][0], ah[m][1], ah[m][2], ah[m][3], bh0[nt], bh1[nt]);
                    mma16816(acc[m][nt], al[m][0], al[m][1], al[m][2], al[m][3], bh0[nt], bh1[nt]);
                    mma16816(acc[m][nt], ah[m][0], ah[m][1], ah[m][2], ah[m][3], bl0[nt], bl1[nt]);
                }
        }
        if (ch + 1 < 16)
            sim_build16(smsu + ((ch + 1) & 1) * (2 * SQ_TILE),
                        smsu + ((ch + 1) & 1) * (2 * SQ_TILE) + SQ_TILE,
                        q, k0g + (ch + 1) * 32, bc, bk2);
        __syncthreads();
    }

    float* dst = g_simp + (((size_t)(b * 32 + split)) * C_ * C_);
    #pragma unroll
    for (int m = 0; m < 4; m++) {
        const int c0 = warpM * 64 + m * 16 + gp;
        #pragma unroll
        for (int nt = 0; nt < 4; nt++) {
            const int d = warpN * 32 + nt * 8 + tg * 2;
            *(float2*)(dst + (size_t)c0 * C_ + d)       = make_float2(acc[m][nt].x, acc[m][nt].y);
            *(float2*)(dst + (size_t)(c0 + 8) * C_ + d) = make_float2(acc[m][nt].z, acc[m][nt].w);
        }
    }
}

// ===== 6. softmax(max - sim) == exp(min - sim)/sum =========================
__global__ void softmax_kernel() {
    const int c = blockIdx.x, b = blockIdx.y;
    const int d = threadIdx.x;
    float s = 0.f;
    #pragma unroll 8
    for (int sp = 0; sp < 32; sp++)
        s += g_simp[(((size_t)(b * 32 + sp)) * C_ + c) * C_ + d];

    __shared__ float red[128];
    red[d] = s;
    __syncthreads();
    for (int st = 64; st > 0; st >>= 1) {
        if (d < st) red[d] = fminf(red[d], red[d + st]);
        __syncthreads();
    }
    const float mn = red[0];
    __syncthreads();
    const float e = expf(mn - s);
    red[d] = e;
    __syncthreads();
    for (int st = 64; st > 0; st >>= 1) {
        if (d < st) red[d] += red[d + st];
        __syncthreads();
    }
    g_p[(b * C_ + c) * C_ + d] = e / red[0];
}

// ===== 7. feat = P @ Q via fp16 mma; out = gamma*feat + y ==================
// P tile [c=128][d2=16] stride 20; Q tile [d2=16][n=128] stride 136.
__global__ void __launch_bounds__(256, 2)
feat_mma_kernel(const float* __restrict__ gamma, float* __restrict__ out) {
    extern __shared__ uint32_t fmsu[];
    uint32_t* Ph = fmsu;
    uint32_t* Pl = fmsu + SQ_TILE;
    uint32_t* Qh = fmsu + 2 * SQ_TILE;
    uint32_t* Ql = Qh + CB_TILE;

    const int tid = threadIdx.x;
    const int wid = tid >> 5, lane = tid & 31;
    const int warpM = wid >> 2, warpN = wid & 3;
    const int tg = lane & 3, gp = lane >> 2;
    const int n0 = blockIdx.x * 128, b = blockIdx.y;

    const float* qsrc = g_y + (size_t)b * C_ * N_;
    const float* psrc = g_p + (size_t)b * C_ * C_;

    float4 acc[4][4];
    #pragma unroll
    for (int m = 0; m < 4; m++)
        #pragma unroll
        for (int n = 0; n < 4; n++) acc[m][n] = make_float4(0.f, 0.f, 0.f, 0.f);

    const int pc = tid >> 1, pk2 = (tid & 1) * 8;   // P builder
    const int qd2 = tid >> 4, qns = (tid & 15) * 8; // Q builder

    for (int ch = 0; ch < 4; ch++) {
        const int d0 = ch * 32;
        __syncthreads();
        // P tile: pairs over d (contiguous)
        {
            const float* src = psrc + (size_t)pc * C_ + d0 + 2 * pk2;
            #pragma unroll
            for (int e = 0; e < 8; e++) {
                float2 v = *(const float2*)(src + 2 * e);
                __half h0, l0, h1, l1;
                split_h(v.x, h0, l0);
                split_h(v.y, h1, l1);
                Ph[pc * SQ_STR + pk2 + e] = pack2(h0, h1);
                Pl[pc * SQ_STR + pk2 + e] = pack2(l0, l1);
            }
        }
        // Q tile: pairs over d (rows) — load two rows, interleave
        {
            const int r0 = d0 + 2 * qd2;
            const float* s0 = qsrc + (size_t)r0 * N_ + n0 + qns;
            const float* s1 = s0 + N_;
            float4 v0a = *(const float4*)s0;
            float4 v0b = *(const float4*)(s0 + 4);
            float4 v1a = *(const float4*)s1;
            float4 v1b = *(const float4*)(s1 + 4);
            const float v0[8] = {v0a.x, v0a.y, v0a.z, v0a.w, v0b.x, v0b.y, v0b.z, v0b.w};
            const float v1[8] = {v1a.x, v1a.y, v1a.z, v1a.w, v1b.x, v1b.y, v1b.z, v1b.w};
            #pragma unroll
            for (int e = 0; e < 8; e++) {
                __half h0, l0, h1, l1;
                split_h(v0[e], h0, l0);
                split_h(v1[e], h1, l1);
                Qh[qd2 * CB_STR + qns + e] = pack2(h0, h1);
                Ql[qd2 * CB_STR + qns + e] = pack2(l0, l1);
            }
        }
        __syncthreads();

        #pragma unroll
        for (int j2 = 0; j2 < 2; j2++) {
            const int k2a = j2 * 8 + tg;
            uint32_t ah[4][4], al[4][4];
            #pragma unroll
            for (int m = 0; m < 4; m++) {
                const int row = warpM * 64 + m * 16 + gp;
                ah[m][0] = Ph[row * SQ_STR + k2a];
                ah[m][1] = Ph[(row + 8) * SQ_STR + k2a];
                ah[m][2] = Ph[row * SQ_STR + k2a + 4];
                ah[m][3] = Ph[(row + 8) * SQ_STR + k2a + 4];
                al[m][0] = Pl[row * SQ_STR + k2a];
                al[m][1] = Pl[(row + 8) * SQ_STR + k2a];
                al[m][2] = Pl[row * SQ_STR + k2a + 4];
                al[m][3] = Pl[(row + 8) * SQ_STR + k2a + 4];
            }
            uint32_t bh0[4], bh1[4], bl0[4], bl1[4];
            #pragma unroll
            for (int nt = 0; nt < 4; nt++) {
                const int cb = warpN * 32 + nt * 8 + gp;
                bh0[nt] = Qh[(k2a    ) * CB_STR + cb];
                bh1[nt] = Qh[(k2a + 4) * CB_STR + cb];
                bl0[nt] = Ql[(k2a    ) * CB_STR + cb];
                bl1[nt] = Ql[(k2a + 4) * CB_STR + cb];
            }
            #pragma unroll
            for (int m = 0; m < 4; m++)
                #pragma unroll
                for (int nt = 0; nt < 4; nt++) {
                    mma16816(acc[m][nt], ah[m][0], ah[m][1], ah[m][2], ah[m][3], bh0[nt], bh1[nt]);
                    mma16816(acc[m][nt], al[m][0], al[m][1], al[m][2], al[m][3], bh0[nt], bh1[nt]);
                    mma16816(acc[m][nt], ah[m][0], ah[m][1], ah[m][2], ah[m][3], bl0[nt], bl1[nt]);
                }
        }
    }

    const float g0 = gamma[0];
    #pragma unroll
    for (int m = 0; m < 4; m++) {
        const int co0 = warpM * 64 + m * 16 + gp;
        const int co1 = co0 + 8;
        #pragma unroll
        for (int nt = 0; nt < 4; nt++) {
            const int w = warpN * 32 + nt * 8 + tg * 2;
            const size_t a0 = ((size_t)(b * C_ + co0)) * N_ + n0 + w;
            const size_t a1 = ((size_t)(b * C_ + co1)) * N_ + n0 + w;
            float2 y0 = *(const float2*)(g_y + a0);
            float2 y1 = *(const float2*)(g_y + a1);
            float2 o0, o1;
            o0.x = g0 * acc[m][nt].x + y0.x;  o0.y = g0 * acc[m][nt].y + y0.y;
            o1.x = g0 * acc[m][nt].z + y1.x;  o1.y = g0 * acc[m][nt].w + y1.y;
            *(float2*)(out + a0) = o0;
            *(float2*)(out + a1) = o1;
        }
    }
}

// ===== launch ==============================================================
extern "C" void kernel_launch(void* const* d_in, const int* in_sizes, int n_in,
                              void* d_out, int out_size) {
    const float* x1       = (const float*)d_in[0];
    const float* x2       = (const float*)d_in[1];
    const float* se_w1    = (const float*)d_in[2];
    const float* se_w2    = (const float*)d_in[3];
    const float* conv_w   = (const float*)d_in[4];
    const float* bn_gamma = (const float*)d_in[5];
    const float* bn_beta  = (const float*)d_in[6];
    const float* bn_mean  = (const float*)d_in[7];
    const float* bn_var   = (const float*)d_in[8];
    const float* gamma    = (const float*)d_in[9];
    float* out = (float*)d_out;

    const int cv_smem   = 4 * CB_TILE * 4;                 // 34816
    const int sim_smem  = 4 * SQ_TILE * 4;                 // 40960
    const int feat_smem = (2 * SQ_TILE + 2 * CB_TILE) * 4; // 37888

    prep_wf16_kernel<<<(144 * 8 * 2 * 32 + 255) / 256, 256>>>(conv_w);
    avgpool_kernel<<<B_ * C2_, 256>>>(x1, x2);
    se_mlp_kernel<<<1, C2_>>>(se_w1, se_w2);
    conv_mma_kernel<<<dim3(HW_, B_), 256, cv_smem>>>(x1, x2, bn_gamma, bn_beta, bn_mean, bn_var);
    sim_mma_kernel<<<dim3(32, B_), 256, sim_smem>>>();
    softmax_kernel<<<dim3(C_, B_), 128>>>();
    feat_mma_kernel<<<dim3(N_ / 128, B_), 256, feat_smem>>>(gamma, out);
}

// round 8
// speedup vs baseline: 3.1591x; 1.3990x over previous
#include <cuda_runtime.h>
#include <cuda_fp16.h>
#include <cstdint>
#include <math.h>

// Shapes: B=8, C=128, 2C=256, H=W=128, N=H*W=16384
#define B_ 8
#define C_ 128
#define C2_ 256
#define HW_ 128
#define N_ 16384
#define EPS_ 1e-5f

// ===================== fp16 split helpers ==================================
__device__ __forceinline__ void split_h(float v, __half& h, __half& l) {
    h = __float2half_rn(v);
    l = __float2half_rn(v - __half2float(h));
}
__device__ __forceinline__ uint32_t pack2(__half a, __half b) {
    return (uint32_t)__half_as_ushort(a) | ((uint32_t)__half_as_ushort(b) << 16);
}
__device__ __forceinline__ void mma16816(float4& d, uint32_t a0, uint32_t a1,
                                         uint32_t a2, uint32_t a3,
                                         uint32_t b0, uint32_t b1) {
    asm volatile(
        "mma.sync.aligned.m16n8k16.row.col.f32.f16.f16.f32 "
        "{%0,%1,%2,%3}, {%4,%5,%6,%7}, {%8,%9}, {%0,%1,%2,%3};"
        : "+f"(d.x), "+f"(d.y), "+f"(d.z), "+f"(d.w)
        : "r"(a0), "r"(a1), "r"(a2), "r"(a3), "r"(b0), "r"(b1));
}

// ===================== device scratch ======================================
__device__ __align__(16) uint4 g_wf16[144 * 8 * 2 * 32];
__device__ float g_avg[B_ * C2_];
__device__ float g_se[B_ * C2_];
__device__ __align__(16) float g_y[(size_t)B_ * C_ * N_];
__device__ __align__(16) float g_simp[(size_t)B_ * 32 * C_ * C_];
__device__ __align__(16) float g_p[B_ * C_ * C_];

// ===== 1. weight prep: conv_w [co][ci][tap] -> fp16 k16 fragments ==========
__global__ void prep_wf16_kernel(const float* __restrict__ conv_w) {
    int idx = blockIdx.x * blockDim.x + threadIdx.x;
    if (idx >= 144 * 8 * 2 * 32) return;
    int lane = idx & 31;
    int s    = (idx >> 5) & 1;
    int mt   = (idx >> 6) & 7;
    int ks2  = idx >> 9;
    int j2   = ks2 & 1;
    int cib  = (ks2 >> 1) & 7;
    int tap  = ks2 >> 4;
    int tg = lane & 3, gp = lane >> 2;
    int co  = mt * 16 + gp;
    int ci0 = cib * 32 + j2 * 16;

    float w[8];
    w[0] = conv_w[((co    ) * C2_ + ci0 + 2 * tg    ) * 9 + tap];
    w[1] = conv_w[((co    ) * C2_ + ci0 + 2 * tg + 1) * 9 + tap];
    w[2] = conv_w[((co + 8) * C2_ + ci0 + 2 * tg    ) * 9 + tap];
    w[3] = conv_w[((co + 8) * C2_ + ci0 + 2 * tg + 1) * 9 + tap];
    w[4] = conv_w[((co    ) * C2_ + ci0 + 2 * tg + 8) * 9 + tap];
    w[5] = conv_w[((co    ) * C2_ + ci0 + 2 * tg + 9) * 9 + tap];
    w[6] = conv_w[((co + 8) * C2_ + ci0 + 2 * tg + 8) * 9 + tap];
    w[7] = conv_w[((co + 8) * C2_ + ci0 + 2 * tg + 9) * 9 + tap];

    __half h[8], l[8];
    #pragma unroll
    for (int i = 0; i < 8; i++) split_h(w[i], h[i], l[i]);

    uint4 v;
    if (s == 0) {
        v.x = pack2(h[0], h[1]); v.y = pack2(h[2], h[3]);
        v.z = pack2(h[4], h[5]); v.w = pack2(h[6], h[7]);
    } else {
        v.x = pack2(l[0], l[1]); v.y = pack2(l[2], l[3]);
        v.z = pack2(l[4], l[5]); v.w = pack2(l[6], l[7]);
    }
    g_wf16[idx] = v;
}

// ===== 2. global average pool ==============================================
__global__ void avgpool_kernel(const float* __restrict__ x1,
                               const float* __restrict__ x2) {
    int bc = blockIdx.x;
    int b = bc >> 8, c = bc & 255;
    const float* src = (c < C_) ? (x1 + ((size_t)(b * C_ + c)) * N_)
                                : (x2 + ((size_t)(b * C_ + (c - C_))) * N_);
    float s = 0.f;
    const float4* s4 = (const float4*)src;
    for (int i = threadIdx.x; i < N_ / 4; i += 256) {
        float4 v = s4[i];
        s += v.x + v.y + v.z + v.w;
    }
    for (int o = 16; o; o >>= 1) s += __shfl_down_sync(0xffffffffu, s, o);
    __shared__ float ws[8];
    int lane = threadIdx.x & 31, wid = threadIdx.x >> 5;
    if (lane == 0) ws[wid] = s;
    __syncthreads();
    if (threadIdx.x == 0) {
        float t = 0.f;
        #pragma unroll
        for (int i = 0; i < 8; i++) t += ws[i];
        g_avg[bc] = t * (1.f / (float)N_);
    }
}

// ===== 3. SE MLP ===========================================================
__global__ void se_mlp_kernel(const float* __restrict__ se_w1,
                              const float* __restrict__ se_w2) {
    __shared__ float avg_s[C2_];
    __shared__ float h_s[32];
    int tid = threadIdx.x;
    for (int b = 0; b < B_; b++) {
        avg_s[tid] = g_avg[b * C2_ + tid];
        __syncthreads();
        if (tid < 32) {
            float s = 0.f;
            #pragma unroll 8
            for (int k = 0; k < C2_; k++) s += avg_s[k] * se_w1[tid * C2_ + k];
            h_s[tid] = fmaxf(s, 0.f);
        }
        __syncthreads();
        {
            float s = 0.f;
            #pragma unroll
            for (int j = 0; j < 32; j++) s += h_s[j] * se_w2[tid * 32 + j];
            g_se[b * C2_ + tid] = 1.f / (1.f + expf(-s));
        }
        __syncthreads();
    }
}

// ===== 4. conv 3x3, fp16 k16, HALO B tile (one build per (hh,cib)) =========
// B tile: [k2=16][wext=0..129] halo layout; tile[wext] = src[wext-1].
// Columns 0 and 129 are statically zero (written once at init).
#define CB_STR 136
#define CB_TILE (16 * CB_STR)   // 2176 u32 per tile

__device__ __forceinline__ void conv_build_halo(
    uint32_t* __restrict__ th, uint32_t* __restrict__ tl,
    const float* __restrict__ x1, const float* __restrict__ x2,
    int b, int hh, int cib, int k2, int seg)
{
    const int ci0 = cib * 32 + 2 * k2;
    const float se0 = g_se[b * C2_ + ci0];
    const float se1 = g_se[b * C2_ + ci0 + 1];
    const float* s0 = ((ci0 < C_) ? (x1 + ((size_t)(b * C_ + ci0)) * N_)
                                  : (x2 + ((size_t)(b * C_ + ci0 - C_)) * N_))
                      + (size_t)hh * HW_ + seg * 8;
    const int ci1 = ci0 + 1;
    const float* s1 = ((ci1 < C_) ? (x1 + ((size_t)(b * C_ + ci1)) * N_)
                                  : (x2 + ((size_t)(b * C_ + ci1 - C_)) * N_))
                      + (size_t)hh * HW_ + seg * 8;
    float4 a0 = ((const float4*)s0)[0];
    float4 a1 = ((const float4*)s0)[1];
    float4 b0 = ((const float4*)s1)[0];
    float4 b1 = ((const float4*)s1)[1];
    const float v0[8] = {a0.x, a0.y, a0.z, a0.w, a1.x, a1.y, a1.z, a1.w};
    const float v1[8] = {b0.x, b0.y, b0.z, b0.w, b1.x, b1.y, b1.z, b1.w};
    uint32_t* dh = th + k2 * CB_STR + 1 + seg * 8;
    uint32_t* dl = tl + k2 * CB_STR + 1 + seg * 8;
    #pragma unroll
    for (int e = 0; e < 8; e++) {
        __half h0, l0, h1, l1;
        split_h(v0[e] * se0, h0, l0);
        split_h(v1[e] * se1, h1, l1);
        dh[e] = pack2(h0, h1);
        dl[e] = pack2(l0, l1);
    }
}

__global__ void __launch_bounds__(256, 2)
conv_mma_kernel(const float* __restrict__ x1, const float* __restrict__ x2,
                const float* __restrict__ bn_gamma, const float* __restrict__ bn_beta,
                const float* __restrict__ bn_mean, const float* __restrict__ bn_var) {
    extern __shared__ uint32_t cvsu[];   // [buf0_hi][buf0_lo][buf1_hi][buf1_lo]

    const int tid = threadIdx.x;
    const int wid = tid >> 5, lane = tid & 31;
    const int warpM = wid >> 2, warpN = wid & 3;
    const int h = blockIdx.x, b = blockIdx.y;

    float4 acc[4][4];
    #pragma unroll
    for (int m = 0; m < 4; m++)
        #pragma unroll
        for (int n = 0; n < 4; n++) acc[m][n] = make_float4(0.f, 0.f, 0.f, 0.f);

    const int bk2 = tid >> 4;           // builder k2 0..15
    const int bseg = tid & 15;          // builder w segment (8 wide)

    const int tg = lane & 3;
    const int gp = lane >> 2;
    const int cbase = warpN * 32 + gp;

    // zero the halo columns (wext = 0 and 129) of all 4 tiles, once
    for (int i = tid; i < 128; i += 256) {
        const int t = i >> 5;           // tile 0..3
        const int r = (i & 31) >> 1;    // k2 row 0..15
        const int c = (i & 1) ? 129 : 0;
        cvsu[t * CB_TILE + r * CB_STR + c] = 0u;
    }

    // valid input rows
    int vh[3], vk[3], nvh = 0;
    #pragma unroll
    for (int dh = -1; dh <= 1; dh++) {
        const int hh = h + dh;
        if (hh >= 0 && hh < HW_) { vh[nvh] = hh; vk[nvh] = dh + 1; nvh++; }
    }
    const int nb = nvh * 8;

    __syncthreads();
    conv_build_halo(cvsu, cvsu + CB_TILE, x1, x2, b, vh[0], 0, bk2, bseg);
    __syncthreads();

    for (int q = 0; q < nb; q++) {
        const int khi = vk[q >> 3], cib = q & 7;
        const uint32_t* th = cvsu + (q & 1) * (2 * CB_TILE);
        const uint32_t* tl = th + CB_TILE;

        #pragma unroll
        for (int kwi = 0; kwi < 3; kwi++) {
            const int tap = khi * 3 + kwi;
            #pragma unroll
            for (int j2 = 0; j2 < 2; j2++) {
                const int ks2 = (tap * 8 + cib) * 2 + j2;
                const int k2a = j2 * 8 + tg;
                const int col = cbase + kwi;

                uint32_t bh0[4], bh1[4], bl0[4], bl1[4];
                #pragma unroll
                for (int nt = 0; nt < 4; nt++) {
                    bh0[nt] = th[(k2a    ) * CB_STR + col + nt * 8];
                    bh1[nt] = th[(k2a + 4) * CB_STR + col + nt * 8];
                    bl0[nt] = tl[(k2a    ) * CB_STR + col + nt * 8];
                    bl1[nt] = tl[(k2a + 4) * CB_STR + col + nt * 8];
                }

                uint4 ah[4];
                #pragma unroll
                for (int m = 0; m < 4; m++)
                    ah[m] = g_wf16[((size_t)(ks2 * 8 + warpM * 4 + m) * 2) * 32 + lane];

                #pragma unroll
                for (int m = 0; m < 4; m++)
                    #pragma unroll
                    for (int nt = 0; nt < 4; nt++)
                        mma16816(acc[m][nt], ah[m].x, ah[m].y, ah[m].z, ah[m].w, bh0[nt], bh1[nt]);

                uint4 al[4];
                #pragma unroll
                for (int m = 0; m < 4; m++)
                    al[m] = g_wf16[((size_t)(ks2 * 8 + warpM * 4 + m) * 2 + 1) * 32 + lane];

                #pragma unroll
                for (int m = 0; m < 4; m++)
                    #pragma unroll
                    for (int nt = 0; nt < 4; nt++)
                        mma16816(acc[m][nt], ah[m].x, ah[m].y, ah[m].z, ah[m].w, bl0[nt], bl1[nt]);

                #pragma unroll
                for (int m = 0; m < 4; m++)
                    #pragma unroll
                    for (int nt = 0; nt < 4; nt++)
                        mma16816(acc[m][nt], al[m].x, al[m].y, al[m].z, al[m].w, bh0[nt], bh1[nt]);
            }
        }

        if (q + 1 < nb) {
            const int q2 = q + 1;
            uint32_t* nh = cvsu + (q2 & 1) * (2 * CB_TILE);
            conv_build_halo(nh, nh + CB_TILE, x1, x2, b, vh[q2 >> 3], q2 & 7, bk2, bseg);
        }
        __syncthreads();
    }

    #pragma unroll
    for (int m = 0; m < 4; m++) {
        const int co0 = warpM * 64 + m * 16 + gp;
        const int co1 = co0 + 8;
        const float inv0 = bn_gamma[co0] * rsqrtf(bn_var[co0] + EPS_);
        const float bia0 = bn_beta[co0] - bn_mean[co0] * inv0;
        const float inv1 = bn_gamma[co1] * rsqrtf(bn_var[co1] + EPS_);
        const float bia1 = bn_beta[co1] - bn_mean[co1] * inv1;
        #pragma unroll
        for (int nt = 0; nt < 4; nt++) {
            const int w = warpN * 32 + nt * 8 + tg * 2;
            float2 v0, v1;
            v0.x = fmaxf(acc[m][nt].x * inv0 + bia0, 0.f);
            v0.y = fmaxf(acc[m][nt].y * inv0 + bia0, 0.f);
            v1.x = fmaxf(acc[m][nt].z * inv1 + bia1, 0.f);
            v1.y = fmaxf(acc[m][nt].w * inv1 + bia1, 0.f);
            *(float2*)(g_y + ((size_t)(b * C_ + co0)) * N_ + (size_t)h * HW_ + w) = v0;
            *(float2*)(g_y + ((size_t)(b * C_ + co1)) * N_ + (size_t)h * HW_ + w) = v1;
        }
    }
}

// ===== 5. sim = Q Q^T via fp16 mma, split-K=32, double-buffered ============
#define SQ_STR 20
#define SQ_TILE (128 * SQ_STR)   // 2560 u32 per tile

__device__ __forceinline__ void sim_build16(uint32_t* __restrict__ qh,
                                            uint32_t* __restrict__ ql,
                                            const float* __restrict__ q,
                                            int kbase, int c, int k2b) {
    const float* src = q + (size_t)c * N_ + kbase + 2 * k2b;
    #pragma unroll
    for (int e = 0; e < 8; e++) {
        float2 v = *(const float2*)(src + 2 * e);
        __half h0, l0, h1, l1;
        split_h(v.x, h0, l0);
        split_h(v.y, h1, l1);
        qh[c * SQ_STR + k2b + e] = pack2(h0, h1);
        ql[c * SQ_STR + k2b + e] = pack2(l0, l1);
    }
}

__global__ void __launch_bounds__(256, 2)
sim_mma_kernel() {
    extern __shared__ uint32_t smsu[];
    const int tid = threadIdx.x;
    const int wid = tid >> 5, lane = tid & 31;
    const int warpM = wid >> 2, warpN = wid & 3;
    const int tg = lane & 3, gp = lane >> 2;
    const int split = blockIdx.x, b = blockIdx.y;
    const float* q = g_y + (size_t)b * C_ * N_;
    const int k0g = split * 512;

    const int bc = tid >> 1, bk2 = (tid & 1) * 8;

    float4 acc[4][4];
    #pragma unroll
    for (int m = 0; m < 4; m++)
        #pragma unroll
        for (int n = 0; n < 4; n++) acc[m][n] = make_float4(0.f, 0.f, 0.f, 0.f);

    sim_build16(smsu, smsu + SQ_TILE, q, k0g, bc, bk2);
    __syncthreads();

    for (int ch = 0; ch < 16; ch++) {
        const uint32_t* qh = smsu + (ch & 1) * (2 * SQ_TILE);
        const uint32_t* ql = qh + SQ_TILE;

        #pragma unroll
        for (int j2 = 0; j2 < 2; j2++) {
            const int k2a = j2 * 8 + tg;
            uint32_t ah[4][4], al[4][4];
            #pragma unroll
            for (int m = 0; m < 4; m++) {
                const int row = warpM * 64 + m * 16 + gp;
                ah[m][0] = qh[row * SQ_STR + k2a];
                ah[m][1] = qh[(row + 8) * SQ_STR + k2a];
                ah[m][2] = qh[row * SQ_STR + k2a + 4];
                ah[m][3] = qh[(row + 8) * SQ_STR + k2a + 4];
                al[m][0] = ql[row * SQ_STR + k2a];
                al[m][1] = ql[(row + 8) * SQ_STR + k2a];
                al[m][2] = ql[row * SQ_STR + k2a + 4];
                al[m][3] = ql[(row + 8) * SQ_STR + k2a + 4];
            }
            uint32_t bh0[4], bh1[4], bl0[4], bl1[4];
            #pragma unroll
            for (int nt = 0; nt < 4; nt++) {
                const int rb = warpN * 32 + nt * 8 + gp;
                bh0[nt] = qh[rb * SQ_STR + k2a];
                bh1[nt] = qh[rb * SQ_STR + k2a + 4];
                bl0[nt] = ql[rb * SQ_STR + k2a];
                bl1[nt] = ql[rb * SQ_STR + k2a + 4];
            }
            #pragma unroll
            for (int m = 0; m < 4; m++)
                #pragma unroll
                for (int nt = 0; nt < 4; nt++) {
                    mma16816(acc[m][nt], ah[m][0], ah[m][1], ah[m][2], ah[m][3], bh0[nt], bh1[nt]);
                    mma16816(acc[m][nt], al[m][0], al[m][1], al[m][2], al[m][3], bh0[nt], bh1[nt]);
                    mma16816(acc[m][nt], ah[m][0], ah[m][1], ah[m][2], ah[m][3], bl0[nt], bl1[nt]);
                }
        }
        if (ch + 1 < 16)
            sim_build16(smsu + ((ch + 1) & 1) * (2 * SQ_TILE),
                        smsu + ((ch + 1) & 1) * (2 * SQ_TILE) + SQ_TILE,
                        q, k0g + (ch + 1) * 32, bc, bk2);
        __syncthreads();
    }

    float* dst = g_simp + (((size_t)(b * 32 + split)) * C_ * C_);
    #pragma unroll
    for (int m = 0; m < 4; m++) {
        const int c0 = warpM * 64 + m * 16 + gp;
        #pragma unroll
        for (int nt = 0; nt < 4; nt++) {
            const int d = warpN * 32 + nt * 8 + tg * 2;
            *(float2*)(dst + (size_t)c0 * C_ + d)       = make_float2(acc[m][nt].x, acc[m][nt].y);
            *(float2*)(dst + (size_t)(c0 + 8) * C_ + d) = make_float2(acc[m][nt].z, acc[m][nt].w);
        }
    }
}

// ===== 6. softmax(max - sim) == exp(min - sim)/sum =========================
__global__ void softmax_kernel() {
    const int c = blockIdx.x, b = blockIdx.y;
    const int d = threadIdx.x;
    float s = 0.f;
    #pragma unroll 8
    for (int sp = 0; sp < 32; sp++)
        s += g_simp[(((size_t)(b * 32 + sp)) * C_ + c) * C_ + d];

    __shared__ float red[128];
    red[d] = s;
    __syncthreads();
    for (int st = 64; st > 0; st >>= 1) {
        if (d < st) red[d] = fminf(red[d], red[d + st]);
        __syncthreads();
    }
    const float mn = red[0];
    __syncthreads();
    const float e = expf(mn - s);
    red[d] = e;
    __syncthreads();
    for (int st = 64; st > 0; st >>= 1) {
        if (d < st) red[d] += red[d + st];
        __syncthreads();
    }
    g_p[(b * C_ + c) * C_ + d] = e / red[0];
}

// ===== 7. feat = P @ Q via fp16 mma; out = gamma*feat + y ==================
__global__ void __launch_bounds__(256, 2)
feat_mma_kernel(const float* __restrict__ gamma, float* __restrict__ out) {
    extern __shared__ uint32_t fmsu[];
    uint32_t* Ph = fmsu;
    uint32_t* Pl = fmsu + SQ_TILE;
    uint32_t* Qh = fmsu + 2 * SQ_TILE;
    uint32_t* Ql = Qh + CB_TILE;

    const int tid = threadIdx.x;
    const int wid = tid >> 5, lane = tid & 31;
    const int warpM = wid >> 2, warpN = wid & 3;
    const int tg = lane & 3, gp = lane >> 2;
    const int n0 = blockIdx.x * 128, b = blockIdx.y;

    const float* qsrc = g_y + (size_t)b * C_ * N_;
    const float* psrc = g_p + (size_t)b * C_ * C_;

    float4 acc[4][4];
    #pragma unroll
    for (int m = 0; m < 4; m++)
        #pragma unroll
        for (int n = 0; n < 4; n++) acc[m][n] = make_float4(0.f, 0.f, 0.f, 0.f);

    const int pc = tid >> 1, pk2 = (tid & 1) * 8;
    const int qd2 = tid >> 4, qns = (tid & 15) * 8;

    for (int ch = 0; ch < 4; ch++) {
        const int d0 = ch * 32;
        __syncthreads();
        {
            const float* src = psrc + (size_t)pc * C_ + d0 + 2 * pk2;
            #pragma unroll
            for (int e = 0; e < 8; e++) {
                float2 v = *(const float2*)(src + 2 * e);
                __half h0, l0, h1, l1;
                split_h(v.x, h0, l0);
                split_h(v.y, h1, l1);
                Ph[pc * SQ_STR + pk2 + e] = pack2(h0, h1);
                Pl[pc * SQ_STR + pk2 + e] = pack2(l0, l1);
            }
        }
        {
            const int r0 = d0 + 2 * qd2;
            const float* s0 = qsrc + (size_t)r0 * N_ + n0 + qns;
            const float* s1 = s0 + N_;
            float4 v0a = *(const float4*)s0;
            float4 v0b = *(const float4*)(s0 + 4);
            float4 v1a = *(const float4*)s1;
            float4 v1b = *(const float4*)(s1 + 4);
            const float v0[8] = {v0a.x, v0a.y, v0a.z, v0a.w, v0b.x, v0b.y, v0b.z, v0b.w};
            const float v1[8] = {v1a.x, v1a.y, v1a.z, v1a.w, v1b.x, v1b.y, v1b.z, v1b.w};
            #pragma unroll
            for (int e = 0; e < 8; e++) {
                __half h0, l0, h1, l1;
                split_h(v0[e], h0, l0);
                split_h(v1[e], h1, l1);
                Qh[qd2 * CB_STR + qns + e] = pack2(h0, h1);
                Ql[qd2 * CB_STR + qns + e] = pack2(l0, l1);
            }
        }
        __syncthreads();

        #pragma unroll
        for (int j2 = 0; j2 < 2; j2++) {
            const int k2a = j2 * 8 + tg;
            uint32_t ah[4][4], al[4][4];
            #pragma unroll
            for (int m = 0; m < 4; m++) {
                const int row = warpM * 64 + m * 16 + gp;
                ah[m][0] = Ph[row * SQ_STR + k2a];
                ah[m][1] = Ph[(row + 8) * SQ_STR + k2a];
                ah[m][2] = Ph[row * SQ_STR + k2a + 4];
                ah[m][3] = Ph[(row + 8) * SQ_STR + k2a + 4];
                al[m][0] = Pl[row * SQ_STR + k2a];
                al[m][1] = Pl[(row + 8) * SQ_STR + k2a];
                al[m][2] = Pl[row * SQ_STR + k2a + 4];
                al[m][3] = Pl[(row + 8) * SQ_STR + k2a + 4];
            }
            uint32_t bh0[4], bh1[4], bl0[4], bl1[4];
            #pragma unroll
            for (int nt = 0; nt < 4; nt++) {
                const int cb = warpN * 32 + nt * 8 + gp;
                bh0[nt] = Qh[(k2a    ) * CB_STR + cb];
                bh1[nt] = Qh[(k2a + 4) * CB_STR + cb];
                bl0[nt] = Ql[(k2a    ) * CB_STR + cb];
                bl1[nt] = Ql[(k2a + 4) * CB_STR + cb];
            }
            #pragma unroll
            for (int m = 0; m < 4; m++)
                #pragma unroll
                for (int nt = 0; nt < 4; nt++) {
                    mma16816(acc[m][nt], ah[m][0], ah[m][1], ah[m][2], ah[m][3], bh0[nt], bh1[nt]);
                    mma16816(acc[m][nt], al[m][0], al[m][1], al[m][2], al[m][3], bh0[nt], bh1[nt]);
                    mma16816(acc[m][nt], ah[m][0], ah[m][1], ah[m][2], ah[m][3], bl0[nt], bl1[nt]);
                }
        }
    }

    const float g0 = gamma[0];
    #pragma unroll
    for (int m = 0; m < 4; m++) {
        const int co0 = warpM * 64 + m * 16 + gp;
        const int co1 = co0 + 8;
        #pragma unroll
        for (int nt = 0; nt < 4; nt++) {
            const int w = warpN * 32 + nt * 8 + tg * 2;
            const size_t a0 = ((size_t)(b * C_ + co0)) * N_ + n0 + w;
            const size_t a1 = ((size_t)(b * C_ + co1)) * N_ + n0 + w;
            float2 y0 = *(const float2*)(g_y + a0);
            float2 y1 = *(const float2*)(g_y + a1);
            float2 o0, o1;
            o0.x = g0 * acc[m][nt].x + y0.x;  o0.y = g0 * acc[m][nt].y + y0.y;
            o1.x = g0 * acc[m][nt].z + y1.x;  o1.y = g0 * acc[m][nt].w + y1.y;
            *(float2*)(out + a0) = o0;
            *(float2*)(out + a1) = o1;
        }
    }
}

// ===== launch ==============================================================
extern "C" void kernel_launch(void* const* d_in, const int* in_sizes, int n_in,
                              void* d_out, int out_size) {
    const float* x1       = (const float*)d_in[0];
    const float* x2       = (const float*)d_in[1];
    const float* se_w1    = (const float*)d_in[2];
    const float* se_w2    = (const float*)d_in[3];
    const float* conv_w   = (const float*)d_in[4];
    const float* bn_gamma = (const float*)d_in[5];
    const float* bn_beta  = (const float*)d_in[6];
    const float* bn_mean  = (const float*)d_in[7];
    const float* bn_var   = (const float*)d_in[8];
    const float* gamma    = (const float*)d_in[9];
    float* out = (float*)d_out;

    const int cv_smem   = 4 * CB_TILE * 4;                 // 34816
    const int sim_smem  = 4 * SQ_TILE * 4;                 // 40960
    const int feat_smem = (2 * SQ_TILE + 2 * CB_TILE) * 4; // 37888

    prep_wf16_kernel<<<(144 * 8 * 2 * 32 + 255) / 256, 256>>>(conv_w);
    avgpool_kernel<<<B_ * C2_, 256>>>(x1, x2);
    se_mlp_kernel<<<1, C2_>>>(se_w1, se_w2);
    conv_mma_kernel<<<dim3(HW_, B_), 256, cv_smem>>>(x1, x2, bn_gamma, bn_beta, bn_mean, bn_var);
    sim_mma_kernel<<<dim3(32, B_), 256, sim_smem>>>();
    softmax_kernel<<<dim3(C_, B_), 128>>>();
    feat_mma_kernel<<<dim3(N_ / 128, B_), 256, feat_smem>>>(gamma, out);
}

// round 9
// speedup vs baseline: 3.2117x; 1.0166x over previous
#include <cuda_runtime.h>
#include <cuda_fp16.h>
#include <cstdint>
#include <math.h>

// Shapes: B=8, C=128, 2C=256, H=W=128, N=H*W=16384
#define B_ 8
#define C_ 128
#define C2_ 256
#define HW_ 128
#define N_ 16384
#define EPS_ 1e-5f

// ===================== fp16 split helpers ==================================
__device__ __forceinline__ void split_h(float v, __half& h, __half& l) {
    h = __float2half_rn(v);
    l = __float2half_rn(v - __half2float(h));
}
__device__ __forceinline__ uint32_t pack2(__half a, __half b) {
    return (uint32_t)__half_as_ushort(a) | ((uint32_t)__half_as_ushort(b) << 16);
}
__device__ __forceinline__ void mma16816(float4& d, uint32_t a0, uint32_t a1,
                                         uint32_t a2, uint32_t a3,
                                         uint32_t b0, uint32_t b1) {
    asm volatile(
        "mma.sync.aligned.m16n8k16.row.col.f32.f16.f16.f32 "
        "{%0,%1,%2,%3}, {%4,%5,%6,%7}, {%8,%9}, {%0,%1,%2,%3};"
        : "+f"(d.x), "+f"(d.y), "+f"(d.z), "+f"(d.w)
        : "r"(a0), "r"(a1), "r"(a2), "r"(a3), "r"(b0), "r"(b1));
}
__device__ __forceinline__ uint32_t smem_u32(const void* p) {
    uint32_t a;
    asm("{ .reg .u64 t; cvta.to.shared.u64 t, %1; cvt.u32.u64 %0, t; }" : "=r"(a) : "l"(p));
    return a;
}
__device__ __forceinline__ void cp_async16(uint32_t dst, const void* src) {
    asm volatile("cp.async.ca.shared.global [%0], [%1], 16;" :: "r"(dst), "l"(src) : "memory");
}
#define CP_COMMIT() asm volatile("cp.async.commit_group;" ::: "memory")
#define CP_WAIT0()  asm volatile("cp.async.wait_group 0;" ::: "memory")

// ===================== device scratch ======================================
__device__ __align__(16) uint4 g_wf16[144 * 8 * 2 * 32];
__device__ float g_avg[B_ * C2_];
__device__ float g_se[B_ * C2_];
__device__ __align__(16) float g_y[(size_t)B_ * C_ * N_];
__device__ __align__(16) float g_simp[(size_t)B_ * 32 * C_ * C_];
__device__ __align__(16) float g_p[B_ * C_ * C_];

// ===== 1. weight prep: conv_w [co][ci][tap] -> fp16 k16 fragments ==========
__global__ void prep_wf16_kernel(const float* __restrict__ conv_w) {
    int idx = blockIdx.x * blockDim.x + threadIdx.x;
    if (idx >= 144 * 8 * 2 * 32) return;
    int lane = idx & 31;
    int s    = (idx >> 5) & 1;
    int mt   = (idx >> 6) & 7;
    int ks2  = idx >> 9;
    int j2   = ks2 & 1;
    int cib  = (ks2 >> 1) & 7;
    int tap  = ks2 >> 4;
    int tg = lane & 3, gp = lane >> 2;
    int co  = mt * 16 + gp;
    int ci0 = cib * 32 + j2 * 16;

    float w[8];
    w[0] = conv_w[((co    ) * C2_ + ci0 + 2 * tg    ) * 9 + tap];
    w[1] = conv_w[((co    ) * C2_ + ci0 + 2 * tg + 1) * 9 + tap];
    w[2] = conv_w[((co + 8) * C2_ + ci0 + 2 * tg    ) * 9 + tap];
    w[3] = conv_w[((co + 8) * C2_ + ci0 + 2 * tg + 1) * 9 + tap];
    w[4] = conv_w[((co    ) * C2_ + ci0 + 2 * tg + 8) * 9 + tap];
    w[5] = conv_w[((co    ) * C2_ + ci0 + 2 * tg + 9) * 9 + tap];
    w[6] = conv_w[((co + 8) * C2_ + ci0 + 2 * tg + 8) * 9 + tap];
    w[7] = conv_w[((co + 8) * C2_ + ci0 + 2 * tg + 9) * 9 + tap];

    __half h[8], l[8];
    #pragma unroll
    for (int i = 0; i < 8; i++) split_h(w[i], h[i], l[i]);

    uint4 v;
    if (s == 0) {
        v.x = pack2(h[0], h[1]); v.y = pack2(h[2], h[3]);
        v.z = pack2(h[4], h[5]); v.w = pack2(h[6], h[7]);
    } else {
        v.x = pack2(l[0], l[1]); v.y = pack2(l[2], l[3]);
        v.z = pack2(l[4], l[5]); v.w = pack2(l[6], l[7]);
    }
    g_wf16[idx] = v;
}

// ===== 2. global average pool ==============================================
__global__ void avgpool_kernel(const float* __restrict__ x1,
                               const float* __restrict__ x2) {
    int bc = blockIdx.x;
    int b = bc >> 8, c = bc & 255;
    const float* src = (c < C_) ? (x1 + ((size_t)(b * C_ + c)) * N_)
                                : (x2 + ((size_t)(b * C_ + (c - C_))) * N_);
    float s = 0.f;
    const float4* s4 = (const float4*)src;
    for (int i = threadIdx.x; i < N_ / 4; i += 256) {
        float4 v = s4[i];
        s += v.x + v.y + v.z + v.w;
    }
    for (int o = 16; o; o >>= 1) s += __shfl_down_sync(0xffffffffu, s, o);
    __shared__ float ws[8];
    int lane = threadIdx.x & 31, wid = threadIdx.x >> 5;
    if (lane == 0) ws[wid] = s;
    __syncthreads();
    if (threadIdx.x == 0) {
        float t = 0.f;
        #pragma unroll
        for (int i = 0; i < 8; i++) t += ws[i];
        g_avg[bc] = t * (1.f / (float)N_);
    }
}

// ===== 3. SE MLP ===========================================================
__global__ void se_mlp_kernel(const float* __restrict__ se_w1,
                              const float* __restrict__ se_w2) {
    __shared__ float avg_s[C2_];
    __shared__ float h_s[32];
    int tid = threadIdx.x;
    for (int b = 0; b < B_; b++) {
        avg_s[tid] = g_avg[b * C2_ + tid];
        __syncthreads();
        if (tid < 32) {
            float s = 0.f;
            #pragma unroll 8
            for (int k = 0; k < C2_; k++) s += avg_s[k] * se_w1[tid * C2_ + k];
            h_s[tid] = fmaxf(s, 0.f);
        }
        __syncthreads();
        {
            float s = 0.f;
            #pragma unroll
            for (int j = 0; j < 32; j++) s += h_s[j] * se_w2[tid * 32 + j];
            g_se[b * C2_ + tid] = 1.f / (1.f + expf(-s));
        }
        __syncthreads();
    }
}

// ===== 4. conv 3x3, fp16 k16, halo B tile + cp.async raw staging ===========
#define CB_STR 136
#define CB_TILE (16 * CB_STR)       // 2176 u32 per packed tile
#define RAW_SLOT 20                 // floats per thread slot (16 used, 16B-aligned stride)
#define RAW_BUF (256 * RAW_SLOT)    // 5120 floats per raw buffer

// direct builder (prologue only) — identical math to round 8
__device__ __forceinline__ void conv_build_halo(
    uint32_t* __restrict__ th, uint32_t* __restrict__ tl,
    const float* __restrict__ x1, const float* __restrict__ x2,
    int b, int hh, int cib, int k2, int seg)
{
    const int ci0 = cib * 32 + 2 * k2;
    const float se0 = g_se[b * C2_ + ci0];
    const float se1 = g_se[b * C2_ + ci0 + 1];
    const float* s0 = ((ci0 < C_) ? (x1 + ((size_t)(b * C_ + ci0)) * N_)
                                  : (x2 + ((size_t)(b * C_ + ci0 - C_)) * N_))
                      + (size_t)hh * HW_ + seg * 8;
    const int ci1 = ci0 + 1;
    const float* s1 = ((ci1 < C_) ? (x1 + ((size_t)(b * C_ + ci1)) * N_)
                                  : (x2 + ((size_t)(b * C_ + ci1 - C_)) * N_))
                      + (size_t)hh * HW_ + seg * 8;
    float4 a0 = ((const float4*)s0)[0];
    float4 a1 = ((const float4*)s0)[1];
    float4 b0 = ((const float4*)s1)[0];
    float4 b1 = ((const float4*)s1)[1];
    const float v0[8] = {a0.x, a0.y, a0.z, a0.w, a1.x, a1.y, a1.z, a1.w};
    const float v1[8] = {b0.x, b0.y, b0.z, b0.w, b1.x, b1.y, b1.z, b1.w};
    uint32_t* dh = th + k2 * CB_STR + 1 + seg * 8;
    uint32_t* dl = tl + k2 * CB_STR + 1 + seg * 8;
    #pragma unroll
    for (int e = 0; e < 8; e++) {
        __half h0, l0, h1, l1;
        split_h(v0[e] * se0, h0, l0);
        split_h(v1[e] * se1, h1, l1);
        dh[e] = pack2(h0, h1);
        dl[e] = pack2(l0, l1);
    }
}

// stage raw input rows for a chunk via cp.async (per-thread private slot)
__device__ __forceinline__ void conv_stage(
    float* __restrict__ rawbuf,
    const float* __restrict__ x1, const float* __restrict__ x2,
    int b, int hh, int cib, int tid)
{
    const int k2 = tid >> 4, seg = tid & 15;
    const int ci0 = cib * 32 + 2 * k2;
    const float* s0 = ((ci0 < C_) ? (x1 + ((size_t)(b * C_ + ci0)) * N_)
                                  : (x2 + ((size_t)(b * C_ + ci0 - C_)) * N_))
                      + (size_t)hh * HW_ + seg * 8;
    const int ci1 = ci0 + 1;
    const float* s1 = ((ci1 < C_) ? (x1 + ((size_t)(b * C_ + ci1)) * N_)
                                  : (x2 + ((size_t)(b * C_ + ci1 - C_)) * N_))
                      + (size_t)hh * HW_ + seg * 8;
    const uint32_t dst = smem_u32(rawbuf + tid * RAW_SLOT);
    cp_async16(dst,      s0);
    cp_async16(dst + 16, s0 + 4);
    cp_async16(dst + 32, s1);
    cp_async16(dst + 48, s1 + 4);
}

// transform staged raw -> packed hi/lo tiles (pure smem; same math/order)
__device__ __forceinline__ void conv_xform(
    uint32_t* __restrict__ th, uint32_t* __restrict__ tl,
    const float* __restrict__ rawbuf, int b, int cib, int tid)
{
    const int k2 = tid >> 4, seg = tid & 15;
    const int ci0 = cib * 32 + 2 * k2;
    const float se0 = g_se[b * C2_ + ci0];
    const float se1 = g_se[b * C2_ + ci0 + 1];
    const float* s = rawbuf + tid * RAW_SLOT;
    float4 a0 = ((const float4*)s)[0];
    float4 a1 = ((const float4*)s)[1];
    float4 b0 = ((const float4*)s)[2];
    float4 b1 = ((const float4*)s)[3];
    const float v0[8] = {a0.x, a0.y, a0.z, a0.w, a1.x, a1.y, a1.z, a1.w};
    const float v1[8] = {b0.x, b0.y, b0.z, b0.w, b1.x, b1.y, b1.z, b1.w};
    uint32_t* dh = th + k2 * CB_STR + 1 + seg * 8;
    uint32_t* dl = tl + k2 * CB_STR + 1 + seg * 8;
    #pragma unroll
    for (int e = 0; e < 8; e++) {
        __half h0, l0, h1, l1;
        split_h(v0[e] * se0, h0, l0);
        split_h(v1[e] * se1, h1, l1);
        dh[e] = pack2(h0, h1);
        dl[e] = pack2(l0, l1);
    }
}

__global__ void __launch_bounds__(256, 2)
conv_mma_kernel(const float* __restrict__ x1, const float* __restrict__ x2,
                const float* __restrict__ bn_gamma, const float* __restrict__ bn_beta,
                const float* __restrict__ bn_mean, const float* __restrict__ bn_var) {
    extern __shared__ uint32_t cvsu[];   // packed[4 tiles] | raw[2 bufs]
    float* raws = (float*)(cvsu + 4 * CB_TILE);

    const int tid = threadIdx.x;
    const int wid = tid >> 5, lane = tid & 31;
    const int warpM = wid >> 2, warpN = wid & 3;
    const int h = blockIdx.x, b = blockIdx.y;

    float4 acc[4][4];
    #pragma unroll
    for (int m = 0; m < 4; m++)
        #pragma unroll
        for (int n = 0; n < 4; n++) acc[m][n] = make_float4(0.f, 0.f, 0.f, 0.f);

    const int bk2 = tid >> 4;
    const int bseg = tid & 15;

    const int tg = lane & 3;
    const int gp = lane >> 2;
    const int cbase = warpN * 32 + gp;

    // zero halo columns (wext = 0 and 129) of all 4 packed tiles
    for (int i = tid; i < 128; i += 256) {
        const int t = i >> 5;
        const int r = (i & 31) >> 1;
        const int c = (i & 1) ? 129 : 0;
        cvsu[t * CB_TILE + r * CB_STR + c] = 0u;
    }

    // valid input rows
    int vh[3], vk[3], nvh = 0;
    #pragma unroll
    for (int dh = -1; dh <= 1; dh++) {
        const int hh = h + dh;
        if (hh >= 0 && hh < HW_) { vh[nvh] = hh; vk[nvh] = dh + 1; nvh++; }
    }
    const int nb = nvh * 8;

    // prologue: chunk 0 direct; stage chunk 1
    conv_build_halo(cvsu, cvsu + CB_TILE, x1, x2, b, vh[0], 0, bk2, bseg);
    if (nb > 1) {
        conv_stage(raws + (1 & 1) * RAW_BUF, x1, x2, b, vh[1 >> 3], 1 & 7, tid);
        CP_COMMIT();
    }
    __syncthreads();

    for (int q = 0; q < nb; q++) {
        const int khi = vk[q >> 3], cib = q & 7;
        const uint32_t* th = cvsu + (q & 1) * (2 * CB_TILE);
        const uint32_t* tl = th + CB_TILE;

        #pragma unroll
        for (int kwi = 0; kwi < 3; kwi++) {
            const int tap = khi * 3 + kwi;
            #pragma unroll
            for (int j2 = 0; j2 < 2; j2++) {
                const int ks2 = (tap * 8 + cib) * 2 + j2;
                const int k2a = j2 * 8 + tg;
                const int col = cbase + kwi;

                uint32_t bh0[4], bh1[4], bl0[4], bl1[4];
                #pragma unroll
                for (int nt = 0; nt < 4; nt++) {
                    bh0[nt] = th[(k2a    ) * CB_STR + col + nt * 8];
                    bh1[nt] = th[(k2a + 4) * CB_STR + col + nt * 8];
                    bl0[nt] = tl[(k2a    ) * CB_STR + col + nt * 8];
                    bl1[nt] = tl[(k2a + 4) * CB_STR + col + nt * 8];
                }

                uint4 ah[4];
                #pragma unroll
                for (int m = 0; m < 4; m++)
                    ah[m] = g_wf16[((size_t)(ks2 * 8 + warpM * 4 + m) * 2) * 32 + lane];

                #pragma unroll
                for (int m = 0; m < 4; m++)
                    #pragma unroll
                    for (int nt = 0; nt < 4; nt++)
                        mma16816(acc[m][nt], ah[m].x, ah[m].y, ah[m].z, ah[m].w, bh0[nt], bh1[nt]);

                uint4 al[4];
                #pragma unroll
                for (int m = 0; m < 4; m++)
                    al[m] = g_wf16[((size_t)(ks2 * 8 + warpM * 4 + m) * 2 + 1) * 32 + lane];

                #pragma unroll
                for (int m = 0; m < 4; m++)
                    #pragma unroll
                    for (int nt = 0; nt < 4; nt++)
                        mma16816(acc[m][nt], ah[m].x, ah[m].y, ah[m].z, ah[m].w, bl0[nt], bl1[nt]);

                #pragma unroll
                for (int m = 0; m < 4; m++)
                    #pragma unroll
                    for (int nt = 0; nt < 4; nt++)
                        mma16816(acc[m][nt], al[m].x, al[m].y, al[m].z, al[m].w, bh0[nt], bh1[nt]);
            }
        }

        if (q + 1 < nb) {
            CP_WAIT0();                       // raw(q+1) landed
            if (q + 2 < nb) {                 // stage q+2 into the now-free buffer
                conv_stage(raws + ((q + 2) & 1) * RAW_BUF, x1, x2,
                           b, vh[(q + 2) >> 3], (q + 2) & 7, tid);
                CP_COMMIT();
            }
            uint32_t* nh = cvsu + ((q + 1) & 1) * (2 * CB_TILE);
            conv_xform(nh, nh + CB_TILE, raws + ((q + 1) & 1) * RAW_BUF,
                       b, (q + 1) & 7, tid);
        }
        __syncthreads();
    }

    #pragma unroll
    for (int m = 0; m < 4; m++) {
        const int co0 = warpM * 64 + m * 16 + gp;
        const int co1 = co0 + 8;
        const float inv0 = bn_gamma[co0] * rsqrtf(bn_var[co0] + EPS_);
        const float bia0 = bn_beta[co0] - bn_mean[co0] * inv0;
        const float inv1 = bn_gamma[co1] * rsqrtf(bn_var[co1] + EPS_);
        const float bia1 = bn_beta[co1] - bn_mean[co1] * inv1;
        #pragma unroll
        for (int nt = 0; nt < 4; nt++) {
            const int w = warpN * 32 + nt * 8 + tg * 2;
            float2 v0, v1;
            v0.x = fmaxf(acc[m][nt].x * inv0 + bia0, 0.f);
            v0.y = fmaxf(acc[m][nt].y * inv0 + bia0, 0.f);
            v1.x = fmaxf(acc[m][nt].z * inv1 + bia1, 0.f);
            v1.y = fmaxf(acc[m][nt].w * inv1 + bia1, 0.f);
            *(float2*)(g_y + ((size_t)(b * C_ + co0)) * N_ + (size_t)h * HW_ + w) = v0;
            *(float2*)(g_y + ((size_t)(b * C_ + co1)) * N_ + (size_t)h * HW_ + w) = v1;
        }
    }
}

// ===== 5. sim = Q Q^T via fp16 mma, split-K=32, double-buffered ============
#define SQ_STR 20
#define SQ_TILE (128 * SQ_STR)   // 2560 u32 per tile

__device__ __forceinline__ void sim_build16(uint32_t* __restrict__ qh,
                                            uint32_t* __restrict__ ql,
                                            const float* __restrict__ q,
                                            int kbase, int c, int k2b) {
    const float* src = q + (size_t)c * N_ + kbase + 2 * k2b;
    #pragma unroll
    for (int e = 0; e < 8; e++) {
        float2 v = *(const float2*)(src + 2 * e);
        __half h0, l0, h1, l1;
        split_h(v.x, h0, l0);
        split_h(v.y, h1, l1);
        qh[c * SQ_STR + k2b + e] = pack2(h0, h1);
        ql[c * SQ_STR + k2b + e] = pack2(l0, l1);
    }
}

__global__ void __launch_bounds__(256, 2)
sim_mma_kernel() {
    extern __shared__ uint32_t smsu[];
    const int tid = threadIdx.x;
    const int wid = tid >> 5, lane = tid & 31;
    const int warpM = wid >> 2, warpN = wid & 3;
    const int tg = lane & 3, gp = lane >> 2;
    const int split = blockIdx.x, b = blockIdx.y;
    const float* q = g_y + (size_t)b * C_ * N_;
    const int k0g = split * 512;

    const int bc = tid >> 1, bk2 = (tid & 1) * 8;

    float4 acc[4][4];
    #pragma unroll
    for (int m = 0; m < 4; m++)
        #pragma unroll
        for (int n = 0; n < 4; n++) acc[m][n] = make_float4(0.f, 0.f, 0.f, 0.f);

    sim_build16(smsu, smsu + SQ_TILE, q, k0g, bc, bk2);
    __syncthreads();

    for (int ch = 0; ch < 16; ch++) {
        const uint32_t* qh = smsu + (ch & 1) * (2 * SQ_TILE);
        const uint32_t* ql = qh + SQ_TILE;

        #pragma unroll
        for (int j2 = 0; j2 < 2; j2++) {
            const int k2a = j2 * 8 + tg;
            uint32_t ah[4][4], al[4][4];
            #pragma unroll
            for (int m = 0; m < 4; m++) {
                const int row = warpM * 64 + m * 16 + gp;
                ah[m][0] = qh[row * SQ_STR + k2a];
                ah[m][1] = qh[(row + 8) * SQ_STR + k2a];
                ah[m][2] = qh[row * SQ_STR + k2a + 4];
                ah[m][3] = qh[(row + 8) * SQ_STR + k2a + 4];
                al[m][0] = ql[row * SQ_STR + k2a];
                al[m][1] = ql[(row + 8) * SQ_STR + k2a];
                al[m][2] = ql[row * SQ_STR + k2a + 4];
                al[m][3] = ql[(row + 8) * SQ_STR + k2a + 4];
            }
            uint32_t bh0[4], bh1[4], bl0[4], bl1[4];
            #pragma unroll
            for (int nt = 0; nt < 4; nt++) {
                const int rb = warpN * 32 + nt * 8 + gp;
                bh0[nt] = qh[rb * SQ_STR + k2a];
                bh1[nt] = qh[rb * SQ_STR + k2a + 4];
                bl0[nt] = ql[rb * SQ_STR + k2a];
                bl1[nt] = ql[rb * SQ_STR + k2a + 4];
            }
            #pragma unroll
            for (int m = 0; m < 4; m++)
                #pragma unroll
                for (int nt = 0; nt < 4; nt++) {
                    mma16816(acc[m][nt], ah[m][0], ah[m][1], ah[m][2], ah[m][3], bh0[nt], bh1[nt]);
                    mma16816(acc[m][nt], al[m][0], al[m][1], al[m][2], al[m][3], bh0[nt], bh1[nt]);
                    mma16816(acc[m][nt], ah[m][0], ah[m][1], ah[m][2], ah[m][3], bl0[nt], bl1[nt]);
                }
        }
        if (ch + 1 < 16)
            sim_build16(smsu + ((ch + 1) & 1) * (2 * SQ_TILE),
                        smsu + ((ch + 1) & 1) * (2 * SQ_TILE) + SQ_TILE,
                        q, k0g + (ch + 1) * 32, bc, bk2);
        __syncthreads();
    }

    float* dst = g_simp + (((size_t)(b * 32 + split)) * C_ * C_);
    #pragma unroll
    for (int m = 0; m < 4; m++) {
        const int c0 = warpM * 64 + m * 16 + gp;
        #pragma unroll
        for (int nt = 0; nt < 4; nt++) {
            const int d = warpN * 32 + nt * 8 + tg * 2;
            *(float2*)(dst + (size_t)c0 * C_ + d)       = make_float2(acc[m][nt].x, acc[m][nt].y);
            *(float2*)(dst + (size_t)(c0 + 8) * C_ + d) = make_float2(acc[m][nt].z, acc[m][nt].w);
        }
    }
}

// ===== 6. softmax(max - sim) == exp(min - sim)/sum =========================
__global__ void softmax_kernel() {
    const int c = blockIdx.x, b = blockIdx.y;
    const int d = threadIdx.x;
    float s = 0.f;
    #pragma unroll 8
    for (int sp = 0; sp < 32; sp++)
        s += g_simp[(((size_t)(b * 32 + sp)) * C_ + c) * C_ + d];

    __shared__ float red[128];
    red[d] = s;
    __syncthreads();
    for (int st = 64; st > 0; st >>= 1) {
        if (d < st) red[d] = fminf(red[d], red[d + st]);
        __syncthreads();
    }
    const float mn = red[0];
    __syncthreads();
    const float e = expf(mn - s);
    red[d] = e;
    __syncthreads();
    for (int st = 64; st > 0; st >>= 1) {
        if (d < st) red[d] += red[d + st];
        __syncthreads();
    }
    g_p[(b * C_ + c) * C_ + d] = e / red[0];
}

// ===== 7. feat = P @ Q via fp16 mma; out = gamma*feat + y ==================
__global__ void __launch_bounds__(256, 2)
feat_mma_kernel(const float* __restrict__ gamma, float* __restrict__ out) {
    extern __shared__ uint32_t fmsu[];
    uint32_t* Ph = fmsu;
    uint32_t* Pl = fmsu + SQ_TILE;
    uint32_t* Qh = fmsu + 2 * SQ_TILE;
    uint32_t* Ql = Qh + CB_TILE;

    const int tid = threadIdx.x;
    const int wid = tid >> 5, lane = tid & 31;
    const int warpM = wid >> 2, warpN = wid & 3;
    const int tg = lane & 3, gp = lane >> 2;
    const int n0 = blockIdx.x * 128, b = blockIdx.y;

    const float* qsrc = g_y + (size_t)b * C_ * N_;
    const float* psrc = g_p + (size_t)b * C_ * C_;

    float4 acc[4][4];
    #pragma unroll
    for (int m = 0; m < 4; m++)
        #pragma unroll
        for (int n = 0; n < 4; n++) acc[m][n] = make_float4(0.f, 0.f, 0.f, 0.f);

    const int pc = tid >> 1, pk2 = (tid & 1) * 8;
    const int qd2 = tid >> 4, qns = (tid & 15) * 8;

    for (int ch = 0; ch < 4; ch++) {
        const int d0 = ch * 32;
        __syncthreads();
        {
            const float* src = psrc + (size_t)pc * C_ + d0 + 2 * pk2;
            #pragma unroll
            for (int e = 0; e < 8; e++) {
                float2 v = *(const float2*)(src + 2 * e);
                __half h0, l0, h1, l1;
                split_h(v.x, h0, l0);
                split_h(v.y, h1, l1);
                Ph[pc * SQ_STR + pk2 + e] = pack2(h0, h1);
                Pl[pc * SQ_STR + pk2 + e] = pack2(l0, l1);
            }
        }
        {
            const int r0 = d0 + 2 * qd2;
            const float* s0 = qsrc + (size_t)r0 * N_ + n0 + qns;
            const float* s1 = s0 + N_;
            float4 v0a = *(const float4*)s0;
            float4 v0b = *(const float4*)(s0 + 4);
            float4 v1a = *(const float4*)s1;
            float4 v1b = *(const float4*)(s1 + 4);
            const float v0[8] = {v0a.x, v0a.y, v0a.z, v0a.w, v0b.x, v0b.y, v0b.z, v0b.w};
            const float v1[8] = {v1a.x, v1a.y, v1a.z, v1a.w, v1b.x, v1b.y, v1b.z, v1b.w};
            #pragma unroll
            for (int e = 0; e < 8; e++) {
                __half h0, l0, h1, l1;
                split_h(v0[e], h0, l0);
                split_h(v1[e], h1, l1);
                Qh[qd2 * CB_STR + qns + e] = pack2(h0, h1);
                Ql[qd2 * CB_STR + qns + e] = pack2(l0, l1);
            }
        }
        __syncthreads();

        #pragma unroll
        for (int j2 = 0; j2 < 2; j2++) {
            const int k2a = j2 * 8 + tg;
            uint32_t ah[4][4], al[4][4];
            #pragma unroll
            for (int m = 0; m < 4; m++) {
                const int row = warpM * 64 + m * 16 + gp;
                ah[m][0] = Ph[row * SQ_STR + k2a];
                ah[m][1] = Ph[(row + 8) * SQ_STR + k2a];
                ah[m][2] = Ph[row * SQ_STR + k2a + 4];
                ah[m][3] = Ph[(row + 8) * SQ_STR + k2a + 4];
                al[m][0] = Pl[row * SQ_STR + k2a];
                al[m][1] = Pl[(row + 8) * SQ_STR + k2a];
                al[m][2] = Pl[row * SQ_STR + k2a + 4];
                al[m][3] = Pl[(row + 8) * SQ_STR + k2a + 4];
            }
            uint32_t bh0[4], bh1[4], bl0[4], bl1[4];
            #pragma unroll
            for (int nt = 0; nt < 4; nt++) {
                const int cb = warpN * 32 + nt * 8 + gp;
                bh0[nt] = Qh[(k2a    ) * CB_STR + cb];
                bh1[nt] = Qh[(k2a + 4) * CB_STR + cb];
                bl0[nt] = Ql[(k2a    ) * CB_STR + cb];
                bl1[nt] = Ql[(k2a + 4) * CB_STR + cb];
            }
            #pragma unroll
            for (int m = 0; m < 4; m++)
                #pragma unroll
                for (int nt = 0; nt < 4; nt++) {
                    mma16816(acc[m][nt], ah[m][0], ah[m][1], ah[m][2], ah[m][3], bh0[nt], bh1[nt]);
                    mma16816(acc[m][nt], al[m][0], al[m][1], al[m][2], al[m][3], bh0[nt], bh1[nt]);
                    mma16816(acc[m][nt], ah[m][0], ah[m][1], ah[m][2], ah[m][3], bl0[nt], bl1[nt]);
                }
        }
    }

    const float g0 = gamma[0];
    #pragma unroll
    for (int m = 0; m < 4; m++) {
        const int co0 = warpM * 64 + m * 16 + gp;
        const int co1 = co0 + 8;
        #pragma unroll
        for (int nt = 0; nt < 4; nt++) {
            const int w = warpN * 32 + nt * 8 + tg * 2;
            const size_t a0 = ((size_t)(b * C_ + co0)) * N_ + n0 + w;
            const size_t a1 = ((size_t)(b * C_ + co1)) * N_ + n0 + w;
            float2 y0 = *(const float2*)(g_y + a0);
            float2 y1 = *(const float2*)(g_y + a1);
            float2 o0, o1;
            o0.x = g0 * acc[m][nt].x + y0.x;  o0.y = g0 * acc[m][nt].y + y0.y;
            o1.x = g0 * acc[m][nt].z + y1.x;  o1.y = g0 * acc[m][nt].w + y1.y;
            *(float2*)(out + a0) = o0;
            *(float2*)(out + a1) = o1;
        }
    }
}

// ===== launch ==============================================================
extern "C" void kernel_launch(void* const* d_in, const int* in_sizes, int n_in,
                              void* d_out, int out_size) {
    const float* x1       = (const float*)d_in[0];
    const float* x2       = (const float*)d_in[1];
    const float* se_w1    = (const float*)d_in[2];
    const float* se_w2    = (const float*)d_in[3];
    const float* conv_w   = (const float*)d_in[4];
    const float* bn_gamma = (const float*)d_in[5];
    const float* bn_beta  = (const float*)d_in[6];
    const float* bn_mean  = (const float*)d_in[7];
    const float* bn_var   = (const float*)d_in[8];
    const float* gamma    = (const float*)d_in[9];
    float* out = (float*)d_out;

    const int cv_smem   = 4 * CB_TILE * 4 + 2 * RAW_BUF * 4; // 34816 + 40960 = 75776
    const int sim_smem  = 4 * SQ_TILE * 4;                   // 40960
    const int feat_smem = (2 * SQ_TILE + 2 * CB_TILE) * 4;   // 37888
    cudaFuncSetAttribute(conv_mma_kernel, cudaFuncAttributeMaxDynamicSharedMemorySize, cv_smem);

    prep_wf16_kernel<<<(144 * 8 * 2 * 32 + 255) / 256, 256>>>(conv_w);
    avgpool_kernel<<<B_ * C2_, 256>>>(x1, x2);
    se_mlp_kernel<<<1, C2_>>>(se_w1, se_w2);
    conv_mma_kernel<<<dim3(HW_, B_), 256, cv_smem>>>(x1, x2, bn_gamma, bn_beta, bn_mean, bn_var);
    sim_mma_kernel<<<dim3(32, B_), 256, sim_smem>>>();
    softmax_kernel<<<dim3(C_, B_), 128>>>();
    feat_mma_kernel<<<dim3(N_ / 128, B_), 256, feat_smem>>>(gamma, out);
}